// round 2
// baseline (speedup 1.0000x reference)
#include <cuda_runtime.h>
#include <cuda_bf16.h>

// Problem constants (fixed by the dataset)
#define NN 4096      // nodes
#define DD 512       // feature dim
#define NW 128       // bitmask words per row (4096/32)

// ---------------- device scratch (no allocation allowed) ----------------
__device__ float    g_buf0[NN * DD];
__device__ float    g_buf1[NN * DD];
__device__ float    g_angles[NN];
__device__ float    g_acc[NN];
__device__ float    g_a1[NN];
__device__ float    g_a2[NN];
__device__ unsigned g_A [NN * NW];
__device__ unsigned g_A2[NN * NW];

// ---------------- zero scratch (deterministic per call) ----------------
__global__ void zero_kernel() {
    int idx = blockIdx.x * blockDim.x + threadIdx.x;
    int total = NN * NW;
    for (int i = idx; i < total; i += gridDim.x * blockDim.x) g_A[i] = 0u;
    if (idx < NN) g_acc[idx] = 0.0f;
}

// ---------------- SGEMM: Y = prelu(X @ W^T + bias, alpha) ----------------
// X: [M,K] row-major, W: [Nout,K] row-major (so X@W^T), Y: [M,Nout]
// Tiles: BM=128, BN=64, BK=16; 256 threads; each thread computes 8x4.
#define BM 128
#define BN 64
#define BK 16

__global__ __launch_bounds__(256) void sgemm_prelu(
    const float* __restrict__ X, const float* __restrict__ W,
    const float* __restrict__ bias, const float* __restrict__ alpha,
    float* __restrict__ Y, int M, int Nout, int Kd)
{
    __shared__ float As[BK][BM];
    __shared__ float Bs[BK][BN];

    const int tid = threadIdx.x;          // 0..255
    const int tx  = tid & 15;             // 0..15 -> n direction (x4)
    const int ty  = tid >> 4;             // 0..15 -> m direction (x8)
    const int bm  = blockIdx.y * BM;
    const int bn  = blockIdx.x * BN;

    float acc[8][4];
#pragma unroll
    for (int i = 0; i < 8; ++i)
#pragma unroll
        for (int j = 0; j < 4; ++j) acc[i][j] = 0.0f;

    const int ar = tid >> 2;              // 0..63
    const int ac = (tid & 3) * 4;         // 0,4,8,12

    for (int k0 = 0; k0 < Kd; k0 += BK) {
        // load A tile (128x16) transposed into As[k][m]; two rows per thread
        float4 av0 = *(const float4*)&X[(size_t)(bm + ar)      * Kd + k0 + ac];
        float4 av1 = *(const float4*)&X[(size_t)(bm + ar + 64) * Kd + k0 + ac];
        As[ac + 0][ar]      = av0.x; As[ac + 1][ar]      = av0.y;
        As[ac + 2][ar]      = av0.z; As[ac + 3][ar]      = av0.w;
        As[ac + 0][ar + 64] = av1.x; As[ac + 1][ar + 64] = av1.y;
        As[ac + 2][ar + 64] = av1.z; As[ac + 3][ar + 64] = av1.w;
        // load B tile (64x16) transposed into Bs[k][n]
        float4 bv = *(const float4*)&W[(size_t)(bn + ar) * Kd + k0 + ac];
        Bs[ac + 0][ar] = bv.x; Bs[ac + 1][ar] = bv.y;
        Bs[ac + 2][ar] = bv.z; Bs[ac + 3][ar] = bv.w;
        __syncthreads();

#pragma unroll
        for (int k = 0; k < BK; ++k) {
            float4 a0 = *(const float4*)&As[k][ty * 8];
            float4 a1 = *(const float4*)&As[k][ty * 8 + 4];
            float4 b0 = *(const float4*)&Bs[k][tx * 4];
            float a[8] = {a0.x, a0.y, a0.z, a0.w, a1.x, a1.y, a1.z, a1.w};
            float b[4] = {b0.x, b0.y, b0.z, b0.w};
#pragma unroll
            for (int i = 0; i < 8; ++i)
#pragma unroll
                for (int j = 0; j < 4; ++j)
                    acc[i][j] = fmaf(a[i], b[j], acc[i][j]);
        }
        __syncthreads();
    }

    const float al = alpha[0];
    float bv[4] = {0.f, 0.f, 0.f, 0.f};
    if (bias) {
#pragma unroll
        for (int j = 0; j < 4; ++j) bv[j] = bias[bn + tx * 4 + j];
    }
#pragma unroll
    for (int i = 0; i < 8; ++i) {
        int m = bm + ty * 8 + i;
        float4 o;
        float v0 = acc[i][0] + bv[0];
        float v1 = acc[i][1] + bv[1];
        float v2 = acc[i][2] + bv[2];
        float v3 = acc[i][3] + bv[3];
        o.x = v0 >= 0.f ? v0 : al * v0;
        o.y = v1 >= 0.f ? v1 : al * v1;
        o.z = v2 >= 0.f ? v2 : al * v2;
        o.w = v3 >= 0.f ? v3 : al * v3;
        *(float4*)&Y[(size_t)m * Nout + bn + tx * 4] = o;
    }
}

// ---------------- output matvec: angles = X @ Wo^T + bo ----------------
__global__ void matvec_kernel(const float* __restrict__ X,
                              const float* __restrict__ Wo,
                              const float* __restrict__ bo)
{
    int warp = (blockIdx.x * blockDim.x + threadIdx.x) >> 5;
    int lane = threadIdx.x & 31;
    if (warp >= NN) return;
    const float* x = X + (size_t)warp * DD;
    float s = 0.f;
#pragma unroll
    for (int it = 0; it < 4; ++it) {
        int k = (lane + it * 32) * 4;
        float4 xv = *(const float4*)&x[k];
        float4 wv = *(const float4*)&Wo[k];
        s = fmaf(xv.x, wv.x, s);
        s = fmaf(xv.y, wv.y, s);
        s = fmaf(xv.z, wv.z, s);
        s = fmaf(xv.w, wv.w, s);
    }
#pragma unroll
    for (int o = 16; o; o >>= 1) s += __shfl_xor_sync(0xffffffffu, s, o);
    if (lane == 0) g_angles[warp] = s + bo[0];
}

// ---------------- edge pass: build bit-adjacency + hop-1 segment sum ----
__global__ void edge_kernel(const int* __restrict__ ei, int E)
{
    int t = blockIdx.x * blockDim.x + threadIdx.x;
    if (t >= E) return;
    int s = ei[t];
    int d = ei[E + t];
    atomicOr(&g_A[s * NW + (d >> 5)], 1u << (d & 31));
    atomicAdd(&g_acc[s], g_angles[d]);   // duplicates count (raw edge list)
}

__global__ void a1_kernel()
{
    int i = blockIdx.x * blockDim.x + threadIdx.x;
    if (i < NN) g_a1[i] = g_angles[i] + 0.25f * g_acc[i];   // (0.5)^2
}

// ---------------- hop 2: A2 = bool(A@A); a2 = a1 + (1/9) * A2 @ a1 -------
// one block of 128 threads per row; thread t owns bit-word t.
__global__ __launch_bounds__(128) void hop2_kernel()
{
    const int i = blockIdx.x;
    const int t = threadIdx.x;
    __shared__ unsigned srow[NW];
    __shared__ float    red[NW];

    srow[t] = g_A[i * NW + t];
    __syncthreads();

    unsigned accw = 0u;
    for (int w = 0; w < NW; ++w) {
        unsigned bits = srow[w];
        while (bits) {
            int b = __ffs(bits) - 1;
            bits &= bits - 1;
            accw |= g_A[(w * 32 + b) * NW + t];
        }
    }
    g_A2[i * NW + t] = accw;

    float p = 0.f;
    unsigned m = accw;
    while (m) {
        int b = __ffs(m) - 1;
        m &= m - 1;
        p += g_a1[t * 32 + b];
    }
    red[t] = p;
    __syncthreads();
#pragma unroll
    for (int s = 64; s; s >>= 1) {
        if (t < s) red[t] += red[t + s];
        __syncthreads();
    }
    if (t == 0) g_a2[i] = g_a1[i] + (1.0f / 9.0f) * red[0];
}

// ---------------- hop 3: A3 = bool(A2@A) == bool(A@A2) ------------------
// Associativity of the boolean semiring: row_i(A3) = OR over 1-hop
// neighbors k of row_k(A2)  (~32 ORs instead of ~900).
__global__ __launch_bounds__(128) void hop3_kernel(float* __restrict__ out)
{
    const int i = blockIdx.x;
    const int t = threadIdx.x;
    __shared__ unsigned srow[NW];
    __shared__ float    red[NW];

    srow[t] = g_A[i * NW + t];
    __syncthreads();

    unsigned accw = 0u;
    for (int w = 0; w < NW; ++w) {
        unsigned bits = srow[w];
        while (bits) {
            int b = __ffs(bits) - 1;
            bits &= bits - 1;
            accw |= g_A2[(w * 32 + b) * NW + t];
        }
    }

    float p = 0.f;
    unsigned m = accw;
    while (m) {
        int b = __ffs(m) - 1;
        m &= m - 1;
        p += g_a2[t * 32 + b];
    }
    red[t] = p;
    __syncthreads();
#pragma unroll
    for (int s = 64; s; s >>= 1) {
        if (t < s) red[t] += red[t + s];
        __syncthreads();
    }
    if (t == 0) out[i] = g_a2[i] + (1.0f / 16.0f) * red[0];
}

// ---------------------------- launch ------------------------------------
extern "C" void kernel_launch(void* const* d_in, const int* in_sizes, int n_in,
                              void* d_out, int out_size)
{
    const float* coeffs = (const float*)d_in[0];
    const int*   eidx   = (const int*)  d_in[1];
    const float* W0     = (const float*)d_in[2];
    const float* b0     = (const float*)d_in[3];
    const float* a0     = (const float*)d_in[4];
    const float* W1     = (const float*)d_in[5];
    const float* a1p    = (const float*)d_in[6];
    const float* W2     = (const float*)d_in[7];
    const float* a2p    = (const float*)d_in[8];
    const float* Wo     = (const float*)d_in[9];
    const float* bo     = (const float*)d_in[10];
    float* out = (float*)d_out;

    const int E = in_sizes[1] / 2;

    // device-symbol scratch pointers
    float *p_buf0, *p_buf1;
    cudaGetSymbolAddress((void**)&p_buf0, g_buf0);
    cudaGetSymbolAddress((void**)&p_buf1, g_buf1);

    // 1) zero A bitmatrix + hop-1 accumulator
    zero_kernel<<<1024, 256>>>();

    // 2) MLP: 3 GEMM+PReLU layers
    dim3 ggrid(DD / BN, NN / BM);
    sgemm_prelu<<<ggrid, 256>>>(coeffs, W0, b0,      a0,  p_buf1, NN, DD, DD);
    sgemm_prelu<<<ggrid, 256>>>(p_buf1, W1, nullptr, a1p, p_buf0, NN, DD, DD);
    sgemm_prelu<<<ggrid, 256>>>(p_buf0, W2, nullptr, a2p, p_buf1, NN, DD, DD);

    // 3) output head -> angles
    matvec_kernel<<<(NN * 32 + 255) / 256, 256>>>(p_buf1, Wo, bo);

    // 4) edges: bit adjacency + hop-1 raw segment sum
    edge_kernel<<<(E + 255) / 256, 256>>>(eidx, E);
    a1_kernel<<<(NN + 255) / 256, 256>>>();

    // 5) hop 2 (materializes A2 bits) and hop 3 (fused, writes output)
    hop2_kernel<<<NN, 128>>>();
    hop3_kernel<<<NN, 128>>>(out);
}

// round 4
// speedup vs baseline: 1.2778x; 1.2778x over previous
#include <cuda_runtime.h>
#include <cuda_bf16.h>
#include <cstdint>

// Problem constants (fixed by the dataset)
#define NN 4096      // nodes
#define DD 512       // feature dim
#define NW 128       // bitmask words per row (4096/32)

// ---------------- device scratch (no allocation allowed) ----------------
__device__ float    g_buf0[NN * DD];
__device__ float    g_buf1[NN * DD];
__device__ float    g_angles[NN];
__device__ float    g_acc[NN];
__device__ float    g_a1[NN];
__device__ float    g_a2[NN];
__device__ unsigned g_A [NN * NW];
__device__ unsigned g_A2[NN * NW];

// ---------------- zero scratch (deterministic per call) ----------------
__global__ void zero_kernel() {
    int idx = blockIdx.x * blockDim.x + threadIdx.x;
    int total = NN * NW;
    for (int i = idx; i < total; i += gridDim.x * blockDim.x) g_A[i] = 0u;
    if (idx < NN) g_acc[idx] = 0.0f;
}

// ======================================================================
//  3xTF32 split-precision GEMM via mma.sync (portable to base sm_103):
//     Y = prelu(X @ W^T + bias, alpha)
//  X: [4096,512] row-major, W: [512,512] row-major (K-major both).
//  CTA: 128(M) x 128(N), 256 threads (8 warps, 2x4), warp: 64x32.
//  K chunks of 32; smem holds hi/lo tf32 splits, stride-36 padding.
// ======================================================================
#define BM 128
#define BN 128
#define BK 32
#define LDSF 36                 // padded row stride in floats
#define CHUNK_F4 1024           // (128 rows * 32 cols) / 4 per operand

__device__ __forceinline__ float tf32_hi(float x) {
    float h;
    asm("cvt.rna.tf32.f32 %0, %1;" : "=f"(h) : "f"(x));
    return h;
}

__device__ __forceinline__ void mma_tf32_16n8k8(
    float c[4], const uint32_t a[4], const uint32_t b[2])
{
    asm volatile(
        "mma.sync.aligned.m16n8k8.row.col.f32.tf32.tf32.f32 "
        "{%0,%1,%2,%3}, {%4,%5,%6,%7}, {%8,%9}, {%0,%1,%2,%3};"
        : "+f"(c[0]), "+f"(c[1]), "+f"(c[2]), "+f"(c[3])
        : "r"(a[0]), "r"(a[1]), "r"(a[2]), "r"(a[3]),
          "r"(b[0]), "r"(b[1]));
}

__global__ __launch_bounds__(256, 1) void tc_gemm(
    const float* __restrict__ X, const float* __restrict__ W,
    const float* __restrict__ bias, const float* __restrict__ alpha,
    float* __restrict__ Y)
{
    extern __shared__ float sm[];
    float* Ah = sm;
    float* Al = Ah + BM * LDSF;
    float* Bh = Al + BM * LDSF;
    float* Bl = Bh + BN * LDSF;

    const int tid  = threadIdx.x;
    const int lane = tid & 31;
    const int wid  = tid >> 5;
    const int g    = lane >> 2;        // group id 0..7
    const int t4   = lane & 3;         // thread in group 0..3
    const int mwarp = (wid >> 2) * 64; // warp m offset (0 or 64)
    const int nwarp = (wid & 3) * 32;  // warp n offset (0..96)
    const int bm = blockIdx.y * BM;
    const int bn = blockIdx.x * BN;

    // staging coords: each thread owns 4 float4 per operand per chunk
    const int srow = tid >> 3;         // 0..31 (x4 iters -> 128 rows)
    const int skq  = tid & 7;          // float4 index within 32-col chunk

    float acc[4][4][4];
#pragma unroll
    for (int i = 0; i < 4; ++i)
#pragma unroll
        for (int j = 0; j < 4; ++j)
#pragma unroll
            for (int q = 0; q < 4; ++q) acc[i][j][q] = 0.0f;

    // prefetch chunk 0
    float4 pa[4], pb[4];
#pragma unroll
    for (int i = 0; i < 4; ++i) {
        int r = srow + i * 32;
        pa[i] = *(const float4*)(X + (size_t)(bm + r) * DD + skq * 4);
        pb[i] = *(const float4*)(W + (size_t)(bn + r) * DD + skq * 4);
    }

    for (int kc = 0; kc < DD / BK; ++kc) {
        // ---- store prefetched chunk to smem as hi/lo splits ----
#pragma unroll
        for (int i = 0; i < 4; ++i) {
            int r = srow + i * 32;
            float4 v = pa[i];
            float4 h, l;
            h.x = tf32_hi(v.x); h.y = tf32_hi(v.y);
            h.z = tf32_hi(v.z); h.w = tf32_hi(v.w);
            l.x = v.x - h.x; l.y = v.y - h.y; l.z = v.z - h.z; l.w = v.w - h.w;
            *(float4*)(Ah + r * LDSF + skq * 4) = h;
            *(float4*)(Al + r * LDSF + skq * 4) = l;
            v = pb[i];
            h.x = tf32_hi(v.x); h.y = tf32_hi(v.y);
            h.z = tf32_hi(v.z); h.w = tf32_hi(v.w);
            l.x = v.x - h.x; l.y = v.y - h.y; l.z = v.z - h.z; l.w = v.w - h.w;
            *(float4*)(Bh + r * LDSF + skq * 4) = h;
            *(float4*)(Bl + r * LDSF + skq * 4) = l;
        }
        __syncthreads();

        // ---- prefetch next chunk while computing ----
        if (kc + 1 < DD / BK) {
            const int koff = (kc + 1) * BK;
#pragma unroll
            for (int i = 0; i < 4; ++i) {
                int r = srow + i * 32;
                pa[i] = *(const float4*)(X + (size_t)(bm + r) * DD + koff + skq * 4);
                pb[i] = *(const float4*)(W + (size_t)(bn + r) * DD + koff + skq * 4);
            }
        }

        // ---- compute: 4 k-steps of 8 ----
#pragma unroll
        for (int ks = 0; ks < 4; ++ks) {
            const int k0 = ks * 8 + t4;
            uint32_t ah[4][4], al[4][4], bh[4][2], bl[4][2];
#pragma unroll
            for (int mt = 0; mt < 4; ++mt) {
                int r0 = mwarp + mt * 16 + g;
                ah[mt][0] = __float_as_uint(Ah[r0 * LDSF + k0]);
                ah[mt][1] = __float_as_uint(Ah[(r0 + 8) * LDSF + k0]);
                ah[mt][2] = __float_as_uint(Ah[r0 * LDSF + k0 + 4]);
                ah[mt][3] = __float_as_uint(Ah[(r0 + 8) * LDSF + k0 + 4]);
                al[mt][0] = __float_as_uint(Al[r0 * LDSF + k0]);
                al[mt][1] = __float_as_uint(Al[(r0 + 8) * LDSF + k0]);
                al[mt][2] = __float_as_uint(Al[r0 * LDSF + k0 + 4]);
                al[mt][3] = __float_as_uint(Al[(r0 + 8) * LDSF + k0 + 4]);
            }
#pragma unroll
            for (int nt = 0; nt < 4; ++nt) {
                int nc = nwarp + nt * 8 + g;
                bh[nt][0] = __float_as_uint(Bh[nc * LDSF + k0]);
                bh[nt][1] = __float_as_uint(Bh[nc * LDSF + k0 + 4]);
                bl[nt][0] = __float_as_uint(Bl[nc * LDSF + k0]);
                bl[nt][1] = __float_as_uint(Bl[nc * LDSF + k0 + 4]);
            }
#pragma unroll
            for (int mt = 0; mt < 4; ++mt)
#pragma unroll
                for (int nt = 0; nt < 4; ++nt) {
                    mma_tf32_16n8k8(acc[mt][nt], ah[mt], bh[nt]);
                    mma_tf32_16n8k8(acc[mt][nt], ah[mt], bl[nt]);
                    mma_tf32_16n8k8(acc[mt][nt], al[mt], bh[nt]);
                }
        }
        __syncthreads();
    }

    // ---- epilogue: bias + PReLU, float2 stores ----
    const float alv = alpha[0];
#pragma unroll
    for (int mt = 0; mt < 4; ++mt) {
        int r0 = bm + mwarp + mt * 16 + g;
#pragma unroll
        for (int nt = 0; nt < 4; ++nt) {
            int cb = bn + nwarp + nt * 8 + 2 * t4;
            float b0 = 0.f, b1 = 0.f;
            if (bias) { b0 = bias[cb]; b1 = bias[cb + 1]; }
            float v0 = acc[mt][nt][0] + b0;
            float v1 = acc[mt][nt][1] + b1;
            float v2 = acc[mt][nt][2] + b0;
            float v3 = acc[mt][nt][3] + b1;
            float2 o0, o1;
            o0.x = v0 >= 0.f ? v0 : alv * v0;
            o0.y = v1 >= 0.f ? v1 : alv * v1;
            o1.x = v2 >= 0.f ? v2 : alv * v2;
            o1.y = v3 >= 0.f ? v3 : alv * v3;
            *(float2*)&Y[(size_t)r0 * DD + cb]       = o0;
            *(float2*)&Y[(size_t)(r0 + 8) * DD + cb] = o1;
        }
    }
}

#define GEMM_SMEM ((2 * BM + 2 * BN) * LDSF * 4)

// ---------------- output matvec: angles = X @ Wo^T + bo ----------------
__global__ void matvec_kernel(const float* __restrict__ X,
                              const float* __restrict__ Wo,
                              const float* __restrict__ bo)
{
    int warp = (blockIdx.x * blockDim.x + threadIdx.x) >> 5;
    int lane = threadIdx.x & 31;
    if (warp >= NN) return;
    const float* x = X + (size_t)warp * DD;
    float s = 0.f;
#pragma unroll
    for (int it = 0; it < 4; ++it) {
        int k = (lane + it * 32) * 4;
        float4 xv = *(const float4*)&x[k];
        float4 wv = *(const float4*)&Wo[k];
        s = fmaf(xv.x, wv.x, s);
        s = fmaf(xv.y, wv.y, s);
        s = fmaf(xv.z, wv.z, s);
        s = fmaf(xv.w, wv.w, s);
    }
#pragma unroll
    for (int o = 16; o; o >>= 1) s += __shfl_xor_sync(0xffffffffu, s, o);
    if (lane == 0) g_angles[warp] = s + bo[0];
}

// ---------------- edge pass: build bit-adjacency + hop-1 segment sum ----
__global__ void edge_kernel(const int* __restrict__ ei, int E)
{
    int t = blockIdx.x * blockDim.x + threadIdx.x;
    if (t >= E) return;
    int s = ei[t];
    int d = ei[E + t];
    atomicOr(&g_A[s * NW + (d >> 5)], 1u << (d & 31));
    atomicAdd(&g_acc[s], g_angles[d]);   // duplicates count (raw edge list)
}

__global__ void a1_kernel()
{
    int i = blockIdx.x * blockDim.x + threadIdx.x;
    if (i < NN) g_a1[i] = g_angles[i] + 0.25f * g_acc[i];   // (0.5)^2
}

// ---------------- hop 2: A2 = bool(A@A); a2 = a1 + (1/9) * A2 @ a1 -------
__global__ __launch_bounds__(128) void hop2_kernel()
{
    const int i = blockIdx.x;
    const int t = threadIdx.x;
    __shared__ unsigned srow[NW];
    __shared__ float    red[NW];

    srow[t] = g_A[i * NW + t];
    __syncthreads();

    unsigned accw = 0u;
    for (int w = 0; w < NW; ++w) {
        unsigned bits = srow[w];
        while (bits) {
            int b = __ffs(bits) - 1;
            bits &= bits - 1;
            accw |= g_A[(w * 32 + b) * NW + t];
        }
    }
    g_A2[i * NW + t] = accw;

    float p = 0.f;
    unsigned m = accw;
    while (m) {
        int b = __ffs(m) - 1;
        m &= m - 1;
        p += g_a1[t * 32 + b];
    }
    red[t] = p;
    __syncthreads();
#pragma unroll
    for (int s = 64; s; s >>= 1) {
        if (t < s) red[t] += red[t + s];
        __syncthreads();
    }
    if (t == 0) g_a2[i] = g_a1[i] + (1.0f / 9.0f) * red[0];
}

// ---------------- hop 3: A3 = bool(A2@A) == bool(A@A2) ------------------
__global__ __launch_bounds__(128) void hop3_kernel(float* __restrict__ out)
{
    const int i = blockIdx.x;
    const int t = threadIdx.x;
    __shared__ unsigned srow[NW];
    __shared__ float    red[NW];

    srow[t] = g_A[i * NW + t];
    __syncthreads();

    unsigned accw = 0u;
    for (int w = 0; w < NW; ++w) {
        unsigned bits = srow[w];
        while (bits) {
            int b = __ffs(bits) - 1;
            bits &= bits - 1;
            accw |= g_A2[(w * 32 + b) * NW + t];
        }
    }

    float p = 0.f;
    unsigned m = accw;
    while (m) {
        int b = __ffs(m) - 1;
        m &= m - 1;
        p += g_a2[t * 32 + b];
    }
    red[t] = p;
    __syncthreads();
#pragma unroll
    for (int s = 64; s; s >>= 1) {
        if (t < s) red[t] += red[t + s];
        __syncthreads();
    }
    if (t == 0) out[i] = g_a2[i] + (1.0f / 16.0f) * red[0];
}

// ---------------------------- launch ------------------------------------
extern "C" void kernel_launch(void* const* d_in, const int* in_sizes, int n_in,
                              void* d_out, int out_size)
{
    const float* coeffs = (const float*)d_in[0];
    const int*   eidx   = (const int*)  d_in[1];
    const float* W0     = (const float*)d_in[2];
    const float* b0     = (const float*)d_in[3];
    const float* a0     = (const float*)d_in[4];
    const float* W1     = (const float*)d_in[5];
    const float* a1p    = (const float*)d_in[6];
    const float* W2     = (const float*)d_in[7];
    const float* a2p    = (const float*)d_in[8];
    const float* Wo     = (const float*)d_in[9];
    const float* bo     = (const float*)d_in[10];
    float* out = (float*)d_out;

    const int E = in_sizes[1] / 2;

    float *p_buf0, *p_buf1;
    cudaGetSymbolAddress((void**)&p_buf0, g_buf0);
    cudaGetSymbolAddress((void**)&p_buf1, g_buf1);

    cudaFuncSetAttribute(tc_gemm, cudaFuncAttributeMaxDynamicSharedMemorySize,
                         GEMM_SMEM);

    // 1) zero A bitmatrix + hop-1 accumulator
    zero_kernel<<<1024, 256>>>();

    // 2) MLP: 3 split-tf32 mma.sync GEMM+PReLU layers
    dim3 ggrid(DD / BN, NN / BM);   // (4, 32) = 128 CTAs
    tc_gemm<<<ggrid, 256, GEMM_SMEM>>>(coeffs, W0, b0,      a0,  p_buf1);
    tc_gemm<<<ggrid, 256, GEMM_SMEM>>>(p_buf1, W1, nullptr, a1p, p_buf0);
    tc_gemm<<<ggrid, 256, GEMM_SMEM>>>(p_buf0, W2, nullptr, a2p, p_buf1);

    // 3) output head -> angles
    matvec_kernel<<<(NN * 32 + 255) / 256, 256>>>(p_buf1, Wo, bo);

    // 4) edges: bit adjacency + hop-1 raw segment sum
    edge_kernel<<<(E + 255) / 256, 256>>>(eidx, E);
    a1_kernel<<<(NN + 255) / 256, 256>>>();

    // 5) hop 2 (materializes A2 bits) and hop 3 (fused, writes output)
    hop2_kernel<<<NN, 128>>>();
    hop3_kernel<<<NN, 128>>>(out);
}

// round 6
// speedup vs baseline: 1.3853x; 1.0841x over previous
#include <cuda_runtime.h>
#include <cuda_bf16.h>
#include <cuda_fp16.h>
#include <cstdint>

// Problem constants (fixed by the dataset)
#define NN 4096      // nodes
#define DD 512       // feature dim
#define NW 128       // bitmask words per row (4096/32)

// ---------------- device scratch (no allocation allowed) ----------------
__device__ float    g_buf0[NN * DD];
__device__ float    g_buf1[NN * DD];
__device__ float    g_angles[NN];
__device__ float    g_acc[NN];
__device__ float    g_a1[NN];
__device__ float    g_a2[NN];
__device__ unsigned g_A [NN * NW];
__device__ unsigned g_A2[NN * NW];

// ---------------- zero scratch (deterministic per call) ----------------
__global__ void zero_kernel() {
    int idx = blockIdx.x * blockDim.x + threadIdx.x;
    int total = NN * NW;
    for (int i = idx; i < total; i += gridDim.x * blockDim.x) g_A[i] = 0u;
    if (idx < NN) g_acc[idx] = 0.0f;
}

// ======================================================================
//  3xFP16 split-precision GEMM via mma.sync.m16n8k16 (base sm_103 OK):
//     Y = prelu(X @ W^T + bias, alpha)
//  x = h + l (h = fp16(x));  D = Ah*Bh + Ah*Bl + Al*Bh  (fp32 accum)
//  CTA: 128(M) x 128(N), 256 threads (8 warps, 2x4), warp: 64x32.
//  K chunks of 32 (2 k-steps of 16); smem: half tiles, stride 40 halves.
// ======================================================================
#define BM 128
#define BN 128
#define BK 32
#define LDSH 40                 // padded row stride in halves (bank-perfect)

__device__ __forceinline__ void mma_f16_16n8k16(
    float c[4], const uint32_t a[4], const uint32_t b[2])
{
    asm volatile(
        "mma.sync.aligned.m16n8k16.row.col.f32.f16.f16.f32 "
        "{%0,%1,%2,%3}, {%4,%5,%6,%7}, {%8,%9}, {%0,%1,%2,%3};"
        : "+f"(c[0]), "+f"(c[1]), "+f"(c[2]), "+f"(c[3])
        : "r"(a[0]), "r"(a[1]), "r"(a[2]), "r"(a[3]),
          "r"(b[0]), "r"(b[1]));
}

// split float4 -> packed fp16 hi pair + lo pair (2 half2 each)
__device__ __forceinline__ void split4(float4 v, uint2& hi, uint2& lo) {
    __half hx = __float2half_rn(v.x), hy = __float2half_rn(v.y);
    __half hz = __float2half_rn(v.z), hw = __float2half_rn(v.w);
    float lx = v.x - __half2float(hx), ly = v.y - __half2float(hy);
    float lz = v.z - __half2float(hz), lw = v.w - __half2float(hw);
    __half2 h01 = __halves2half2(hx, hy), h23 = __halves2half2(hz, hw);
    __half2 l01 = __halves2half2(__float2half_rn(lx), __float2half_rn(ly));
    __half2 l23 = __halves2half2(__float2half_rn(lz), __float2half_rn(lw));
    hi.x = *(uint32_t*)&h01; hi.y = *(uint32_t*)&h23;
    lo.x = *(uint32_t*)&l01; lo.y = *(uint32_t*)&l23;
}

__global__ __launch_bounds__(256, 1) void tc_gemm(
    const float* __restrict__ X, const float* __restrict__ W,
    const float* __restrict__ bias, const float* __restrict__ alpha,
    float* __restrict__ Y)
{
    __shared__ __half Ah[BM * LDSH], Al[BM * LDSH];
    __shared__ __half Bh[BN * LDSH], Bl[BN * LDSH];

    const int tid  = threadIdx.x;
    const int lane = tid & 31;
    const int wid  = tid >> 5;
    const int g    = lane >> 2;        // group id 0..7
    const int t4   = lane & 3;         // thread in group 0..3
    const int mwarp = (wid >> 2) * 64; // warp m offset (0 or 64)
    const int nwarp = (wid & 3) * 32;  // warp n offset (0..96)
    const int bm = blockIdx.y * BM;
    const int bn = blockIdx.x * BN;

    const int srow = tid >> 3;         // 0..31 (x4 iters -> 128 rows)
    const int skq  = tid & 7;          // float4 index within 32-col chunk

    float acc[4][4][4];
#pragma unroll
    for (int i = 0; i < 4; ++i)
#pragma unroll
        for (int j = 0; j < 4; ++j)
#pragma unroll
            for (int q = 0; q < 4; ++q) acc[i][j][q] = 0.0f;

    // prefetch chunk 0
    float4 pa[4], pb[4];
#pragma unroll
    for (int i = 0; i < 4; ++i) {
        int r = srow + i * 32;
        pa[i] = *(const float4*)(X + (size_t)(bm + r) * DD + skq * 4);
        pb[i] = *(const float4*)(W + (size_t)(bn + r) * DD + skq * 4);
    }

    for (int kc = 0; kc < DD / BK; ++kc) {
        // ---- store prefetched chunk to smem as fp16 hi/lo splits ----
#pragma unroll
        for (int i = 0; i < 4; ++i) {
            int r = srow + i * 32;
            uint2 hi, lo;
            split4(pa[i], hi, lo);
            *(uint2*)(Ah + r * LDSH + skq * 4) = hi;
            *(uint2*)(Al + r * LDSH + skq * 4) = lo;
            split4(pb[i], hi, lo);
            *(uint2*)(Bh + r * LDSH + skq * 4) = hi;
            *(uint2*)(Bl + r * LDSH + skq * 4) = lo;
        }
        __syncthreads();

        // ---- prefetch next chunk while computing ----
        if (kc + 1 < DD / BK) {
            const int koff = (kc + 1) * BK;
#pragma unroll
            for (int i = 0; i < 4; ++i) {
                int r = srow + i * 32;
                pa[i] = *(const float4*)(X + (size_t)(bm + r) * DD + koff + skq * 4);
                pb[i] = *(const float4*)(W + (size_t)(bn + r) * DD + koff + skq * 4);
            }
        }

        // ---- compute: 2 k-steps of 16 ----
#pragma unroll
        for (int ks = 0; ks < 2; ++ks) {
            const int k0 = ks * 16 + t4 * 2;
            uint32_t ah[4][4], al[4][4], bh[4][2], bl[4][2];
#pragma unroll
            for (int mt = 0; mt < 4; ++mt) {
                int r0 = mwarp + mt * 16 + g;
                ah[mt][0] = *(const uint32_t*)(Ah + r0 * LDSH + k0);
                ah[mt][1] = *(const uint32_t*)(Ah + (r0 + 8) * LDSH + k0);
                ah[mt][2] = *(const uint32_t*)(Ah + r0 * LDSH + k0 + 8);
                ah[mt][3] = *(const uint32_t*)(Ah + (r0 + 8) * LDSH + k0 + 8);
                al[mt][0] = *(const uint32_t*)(Al + r0 * LDSH + k0);
                al[mt][1] = *(const uint32_t*)(Al + (r0 + 8) * LDSH + k0);
                al[mt][2] = *(const uint32_t*)(Al + r0 * LDSH + k0 + 8);
                al[mt][3] = *(const uint32_t*)(Al + (r0 + 8) * LDSH + k0 + 8);
            }
#pragma unroll
            for (int nt = 0; nt < 4; ++nt) {
                int nc = nwarp + nt * 8 + g;
                bh[nt][0] = *(const uint32_t*)(Bh + nc * LDSH + k0);
                bh[nt][1] = *(const uint32_t*)(Bh + nc * LDSH + k0 + 8);
                bl[nt][0] = *(const uint32_t*)(Bl + nc * LDSH + k0);
                bl[nt][1] = *(const uint32_t*)(Bl + nc * LDSH + k0 + 8);
            }
#pragma unroll
            for (int mt = 0; mt < 4; ++mt)
#pragma unroll
                for (int nt = 0; nt < 4; ++nt) {
                    mma_f16_16n8k16(acc[mt][nt], ah[mt], bh[nt]);
                    mma_f16_16n8k16(acc[mt][nt], ah[mt], bl[nt]);
                    mma_f16_16n8k16(acc[mt][nt], al[mt], bh[nt]);
                }
        }
        __syncthreads();
    }

    // ---- epilogue: bias + PReLU, float2 stores ----
    const float alv = alpha[0];
#pragma unroll
    for (int mt = 0; mt < 4; ++mt) {
        int r0 = bm + mwarp + mt * 16 + g;
#pragma unroll
        for (int nt = 0; nt < 4; ++nt) {
            int cb = bn + nwarp + nt * 8 + 2 * t4;
            float b0 = 0.f, b1 = 0.f;
            if (bias) { b0 = bias[cb]; b1 = bias[cb + 1]; }
            float v0 = acc[mt][nt][0] + b0;
            float v1 = acc[mt][nt][1] + b1;
            float v2 = acc[mt][nt][2] + b0;
            float v3 = acc[mt][nt][3] + b1;
            float2 o0, o1;
            o0.x = v0 >= 0.f ? v0 : alv * v0;
            o0.y = v1 >= 0.f ? v1 : alv * v1;
            o1.x = v2 >= 0.f ? v2 : alv * v2;
            o1.y = v3 >= 0.f ? v3 : alv * v3;
            *(float2*)&Y[(size_t)r0 * DD + cb]       = o0;
            *(float2*)&Y[(size_t)(r0 + 8) * DD + cb] = o1;
        }
    }
}

// ---------------- output matvec: angles = X @ Wo^T + bo ----------------
__global__ void matvec_kernel(const float* __restrict__ X,
                              const float* __restrict__ Wo,
                              const float* __restrict__ bo)
{
    int warp = (blockIdx.x * blockDim.x + threadIdx.x) >> 5;
    int lane = threadIdx.x & 31;
    if (warp >= NN) return;
    const float* x = X + (size_t)warp * DD;
    float s = 0.f;
#pragma unroll
    for (int it = 0; it < 4; ++it) {
        int k = (lane + it * 32) * 4;
        float4 xv = *(const float4*)&x[k];
        float4 wv = *(const float4*)&Wo[k];
        s = fmaf(xv.x, wv.x, s);
        s = fmaf(xv.y, wv.y, s);
        s = fmaf(xv.z, wv.z, s);
        s = fmaf(xv.w, wv.w, s);
    }
#pragma unroll
    for (int o = 16; o; o >>= 1) s += __shfl_xor_sync(0xffffffffu, s, o);
    if (lane == 0) g_angles[warp] = s + bo[0];
}

// ---------------- edge pass: build bit-adjacency + hop-1 segment sum ----
__global__ void edge_kernel(const int* __restrict__ ei, int E)
{
    int t = blockIdx.x * blockDim.x + threadIdx.x;
    if (t >= E) return;
    int s = ei[t];
    int d = ei[E + t];
    atomicOr(&g_A[s * NW + (d >> 5)], 1u << (d & 31));
    atomicAdd(&g_acc[s], g_angles[d]);   // duplicates count (raw edge list)
}

__global__ void a1_kernel()
{
    int i = blockIdx.x * blockDim.x + threadIdx.x;
    if (i < NN) g_a1[i] = g_angles[i] + 0.25f * g_acc[i];   // (0.5)^2
}

// ======================================================================
//  Hop kernels: deterministic neighbor-list extraction (prefix sum) +
//  MLP-4 unrolled row-OR loop + fully-unrolled masked gather.
// ======================================================================
#define NBR_CAP 4096   // hard upper bound (dedup'd bits over 4096 nodes)

// shared between both hop kernels' structure
template <bool STORE_A2>
__device__ __forceinline__ void hop_body(
    const unsigned* __restrict__ nbrmat,   // rows to OR (g_A or g_A2)
    const float*    __restrict__ vec,      // vector to gather (g_a1 or g_a2)
    float scale, float* __restrict__ dst)  // output scalar array
{
    const int i = blockIdx.x;
    const int t = threadIdx.x;  // 0..127

    __shared__ unsigned short s_nbr[NBR_CAP];
    __shared__ int   s_wtot[4];
    __shared__ int   s_deg;
    __shared__ float s_red[NW];

    // --- extract this row's neighbor list, deterministic order ---
    unsigned mybits = g_A[i * NW + t];
    int cnt = __popc(mybits);
    int incl = cnt;
#pragma unroll
    for (int o = 1; o < 32; o <<= 1) {
        int v = __shfl_up_sync(0xffffffffu, incl, o);
        if ((t & 31) >= o) incl += v;
    }
    if ((t & 31) == 31) s_wtot[t >> 5] = incl;
    __syncthreads();
    int base = incl - cnt;
#pragma unroll
    for (int w = 0; w < 4; ++w)
        if (w < (t >> 5)) base += s_wtot[w];
    int pos = base;
    unsigned bb = mybits;
    while (bb) {
        int b = __ffs(bb) - 1;
        bb &= bb - 1;
        s_nbr[pos++] = (unsigned short)(t * 32 + b);
    }
    if (t == 127) s_deg = base + cnt;
    __syncthreads();
    const int deg = s_deg;

    // --- OR the neighbor rows (word t), 4-way ILP ---
    unsigned accw = 0u;
    int j = 0;
    for (; j + 4 <= deg; j += 4) {
        int n0 = s_nbr[j], n1 = s_nbr[j + 1], n2 = s_nbr[j + 2], n3 = s_nbr[j + 3];
        unsigned v0 = nbrmat[n0 * NW + t];
        unsigned v1 = nbrmat[n1 * NW + t];
        unsigned v2 = nbrmat[n2 * NW + t];
        unsigned v3 = nbrmat[n3 * NW + t];
        accw |= (v0 | v1) | (v2 | v3);
    }
    for (; j < deg; ++j) accw |= nbrmat[s_nbr[j] * NW + t];

    if (STORE_A2) g_A2[i * NW + t] = accw;

    // --- masked gather: sum vec over set bits (exact: +0.0f is identity) ---
    float p = 0.f;
    const float* vb = vec + t * 32;
#pragma unroll
    for (int b = 0; b < 32; ++b)
        p += vb[b] * (float)((accw >> b) & 1u);

    s_red[t] = p;
    __syncthreads();
#pragma unroll
    for (int s = 64; s; s >>= 1) {
        if (t < s) s_red[t] += s_red[t + s];
        __syncthreads();
    }
    if (t == 0) dst[i] = vec[i] + scale * s_red[0];
}

__global__ __launch_bounds__(128) void hop2_kernel()
{
    hop_body<true>(g_A, g_a1, 1.0f / 9.0f, g_a2);
}

__global__ __launch_bounds__(128) void hop3_kernel(float* __restrict__ out)
{
    hop_body<false>(g_A2, g_a2, 1.0f / 16.0f, out);
}

// ---------------------------- launch ------------------------------------
extern "C" void kernel_launch(void* const* d_in, const int* in_sizes, int n_in,
                              void* d_out, int out_size)
{
    const float* coeffs = (const float*)d_in[0];
    const int*   eidx   = (const int*)  d_in[1];
    const float* W0     = (const float*)d_in[2];
    const float* b0     = (const float*)d_in[3];
    const float* a0     = (const float*)d_in[4];
    const float* W1     = (const float*)d_in[5];
    const float* a1p    = (const float*)d_in[6];
    const float* W2     = (const float*)d_in[7];
    const float* a2p    = (const float*)d_in[8];
    const float* Wo     = (const float*)d_in[9];
    const float* bo     = (const float*)d_in[10];
    float* out = (float*)d_out;

    const int E = in_sizes[1] / 2;

    float *p_buf0, *p_buf1;
    cudaGetSymbolAddress((void**)&p_buf0, g_buf0);
    cudaGetSymbolAddress((void**)&p_buf1, g_buf1);

    // 1) zero A bitmatrix + hop-1 accumulator
    zero_kernel<<<1024, 256>>>();

    // 2) MLP: 3 split-fp16 mma.sync GEMM+PReLU layers
    dim3 ggrid(DD / BN, NN / BM);   // (4, 32) = 128 CTAs
    tc_gemm<<<ggrid, 256>>>(coeffs, W0, b0,      a0,  p_buf1);
    tc_gemm<<<ggrid, 256>>>(p_buf1, W1, nullptr, a1p, p_buf0);
    tc_gemm<<<ggrid, 256>>>(p_buf0, W2, nullptr, a2p, p_buf1);

    // 3) output head -> angles
    matvec_kernel<<<(NN * 32 + 255) / 256, 256>>>(p_buf1, Wo, bo);

    // 4) edges: bit adjacency + hop-1 raw segment sum
    edge_kernel<<<(E + 255) / 256, 256>>>(eidx, E);
    a1_kernel<<<(NN + 255) / 256, 256>>>();

    // 5) hop 2 (materializes A2 bits) and hop 3 (fused, writes output)
    hop2_kernel<<<NN, 128>>>();
    hop3_kernel<<<NN, 128>>>(out);
}

// round 8
// speedup vs baseline: 2.1824x; 1.5754x over previous
#include <cuda_runtime.h>
#include <cuda_bf16.h>
#include <cuda_fp16.h>
#include <cstdint>

// Problem constants (fixed by the dataset)
#define NN 4096      // nodes
#define DD 512       // feature dim
#define NW 128       // bitmask words per row (4096/32)

// ---------------- device scratch (no allocation allowed) ----------------
__device__ float    g_buf0[NN * DD];
__device__ float    g_buf1[NN * DD];
__device__ float    g_angles[NN];
__device__ float    g_acc[NN];
__device__ float    g_a1[NN];
__device__ float    g_a2[NN];
__device__ unsigned g_A [NN * NW];
__device__ unsigned g_A2[NN * NW];

// ---------------- zero scratch (deterministic per call) ----------------
__global__ void zero_kernel() {
    int idx = blockIdx.x * blockDim.x + threadIdx.x;
    int total = NN * NW;
    for (int i = idx; i < total; i += gridDim.x * blockDim.x) g_A[i] = 0u;
    if (idx < NN) g_acc[idx] = 0.0f;
}

// ======================================================================
//  3xFP16 split-precision GEMM via mma.sync.m16n8k16 + ldmatrix:
//     Y = prelu(X @ W^T + bias, alpha)
//  x = h + l (h = fp16(x));  D = Ah*Bh + Ah*Bl + Al*Bh  (fp32 accum)
//  CTA: 128(M) x 128(N), 256 threads (8 warps, 2x4), warp: 64x32.
//  K chunks of 32; double-buffered smem (one barrier per chunk);
//  stride-40-half rows -> ldmatrix conflict-free (banks 20r mod 32).
// ======================================================================
#define BM 128
#define BN 128
#define BK 32
#define LDSH 40                    // padded row stride in halves
#define ARR_H   (BM * LDSH)        // 5120 halves = 10240 B per array
#define BUF_H   (4 * ARR_H)        // halves per buffer (Ah,Al,Bh,Bl)
#define GEMM_SMEM (2 * BUF_H * 2)  // bytes (two buffers)

__device__ __forceinline__ void mma_f16_16n8k16(
    float c[4], const uint32_t a[4], const uint32_t b[2])
{
    asm volatile(
        "mma.sync.aligned.m16n8k16.row.col.f32.f16.f16.f32 "
        "{%0,%1,%2,%3}, {%4,%5,%6,%7}, {%8,%9}, {%0,%1,%2,%3};"
        : "+f"(c[0]), "+f"(c[1]), "+f"(c[2]), "+f"(c[3])
        : "r"(a[0]), "r"(a[1]), "r"(a[2]), "r"(a[3]),
          "r"(b[0]), "r"(b[1]));
}

__device__ __forceinline__ void ldsm_x4(uint32_t r[4], uint32_t addr) {
    asm volatile(
        "ldmatrix.sync.aligned.m8n8.x4.shared.b16 {%0,%1,%2,%3}, [%4];"
        : "=r"(r[0]), "=r"(r[1]), "=r"(r[2]), "=r"(r[3]) : "r"(addr));
}

// split float4 -> packed fp16 hi pair + lo pair (2 half2 each)
__device__ __forceinline__ void split4(float4 v, uint2& hi, uint2& lo) {
    __half hx = __float2half_rn(v.x), hy = __float2half_rn(v.y);
    __half hz = __float2half_rn(v.z), hw = __float2half_rn(v.w);
    float lx = v.x - __half2float(hx), ly = v.y - __half2float(hy);
    float lz = v.z - __half2float(hz), lw = v.w - __half2float(hw);
    __half2 h01 = __halves2half2(hx, hy), h23 = __halves2half2(hz, hw);
    __half2 l01 = __halves2half2(__float2half_rn(lx), __float2half_rn(ly));
    __half2 l23 = __halves2half2(__float2half_rn(lz), __float2half_rn(lw));
    hi.x = *(uint32_t*)&h01; hi.y = *(uint32_t*)&h23;
    lo.x = *(uint32_t*)&l01; lo.y = *(uint32_t*)&l23;
}

__global__ __launch_bounds__(256, 1) void tc_gemm(
    const float* __restrict__ X, const float* __restrict__ W,
    const float* __restrict__ bias, const float* __restrict__ alpha,
    float* __restrict__ Y)
{
    extern __shared__ __half sm[];

    const int tid  = threadIdx.x;
    const int lane = tid & 31;
    const int wid  = tid >> 5;
    const int g    = lane >> 2;        // group id 0..7
    const int t4   = lane & 3;         // thread in group 0..3
    const int mwarp = (wid >> 2) * 64; // warp m offset (0 or 64)
    const int nwarp = (wid & 3) * 32;  // warp n offset (0..96)
    const int bm = blockIdx.y * BM;
    const int bn = blockIdx.x * BN;

    const int srow = tid >> 3;         // 0..31 (x4 iters -> 128 rows)
    const int skq  = tid & 7;          // uint2 index within 32-col chunk

    // ldmatrix per-lane offsets (in halves)
    // A x4 matrices: (m-lo,k-lo),(m-hi,k-lo),(m-lo,k-hi),(m-hi,k-hi)
    const int rowA = lane & 15;
    const int kofA = (lane & 16) ? 8 : 0;
    // B x4 matrices: (n-lo,k-lo),(n-lo,k-hi),(n-hi,k-lo),(n-hi,k-hi)
    const int rowB = (lane & 7) + ((lane & 16) ? 8 : 0);
    const int kofB = (lane & 8) ? 8 : 0;

    const uint32_t smbase = (uint32_t)__cvta_generic_to_shared(sm);

    float acc[4][4][4];
#pragma unroll
    for (int i = 0; i < 4; ++i)
#pragma unroll
        for (int j = 0; j < 4; ++j)
#pragma unroll
            for (int q = 0; q < 4; ++q) acc[i][j][q] = 0.0f;

    // prefetch chunk 0
    float4 pa[4], pb[4];
#pragma unroll
    for (int i = 0; i < 4; ++i) {
        int r = srow + i * 32;
        pa[i] = *(const float4*)(X + (size_t)(bm + r) * DD + skq * 4);
        pb[i] = *(const float4*)(W + (size_t)(bn + r) * DD + skq * 4);
    }

    for (int kc = 0; kc < DD / BK; ++kc) {
        __half* Ah = sm + (kc & 1) * BUF_H;
        __half* Al = Ah + ARR_H;
        __half* Bh = Al + ARR_H;
        __half* Bl = Bh + ARR_H;

        // ---- store prefetched chunk as fp16 hi/lo splits ----
#pragma unroll
        for (int i = 0; i < 4; ++i) {
            int r = srow + i * 32;
            uint2 hi, lo;
            split4(pa[i], hi, lo);
            *(uint2*)(Ah + r * LDSH + skq * 4) = hi;
            *(uint2*)(Al + r * LDSH + skq * 4) = lo;
            split4(pb[i], hi, lo);
            *(uint2*)(Bh + r * LDSH + skq * 4) = hi;
            *(uint2*)(Bl + r * LDSH + skq * 4) = lo;
        }
        __syncthreads();   // single barrier per chunk (double buffer)

        // ---- prefetch next chunk ----
        if (kc + 1 < DD / BK) {
            const int koff = (kc + 1) * BK;
#pragma unroll
            for (int i = 0; i < 4; ++i) {
                int r = srow + i * 32;
                pa[i] = *(const float4*)(X + (size_t)(bm + r) * DD + koff + skq * 4);
                pb[i] = *(const float4*)(W + (size_t)(bn + r) * DD + koff + skq * 4);
            }
        }

        const uint32_t AhU = smbase + (uint32_t)((kc & 1) * BUF_H) * 2u;
        const uint32_t AlU = AhU + ARR_H * 2u;
        const uint32_t BhU = AlU + ARR_H * 2u;
        const uint32_t BlU = BhU + ARR_H * 2u;

        // ---- compute: 2 k-steps of 16 ----
#pragma unroll
        for (int ks = 0; ks < 2; ++ks) {
            uint32_t ah[4][4], al[4][4], bh[4][2], bl[4][2];
            const uint32_t aoff = (uint32_t)(rowA * LDSH + ks * 16 + kofA) * 2u;
            const uint32_t boff = (uint32_t)(rowB * LDSH + ks * 16 + kofB) * 2u;
#pragma unroll
            for (int mt = 0; mt < 4; ++mt) {
                uint32_t mb = (uint32_t)((mwarp + mt * 16) * LDSH) * 2u;
                ldsm_x4(ah[mt], AhU + mb + aoff);
                ldsm_x4(al[mt], AlU + mb + aoff);
            }
#pragma unroll
            for (int p = 0; p < 2; ++p) {
                uint32_t nb = (uint32_t)((nwarp + p * 16) * LDSH) * 2u;
                uint32_t rh[4], rl[4];
                ldsm_x4(rh, BhU + nb + boff);
                ldsm_x4(rl, BlU + nb + boff);
                bh[2 * p][0] = rh[0]; bh[2 * p][1] = rh[1];
                bh[2 * p + 1][0] = rh[2]; bh[2 * p + 1][1] = rh[3];
                bl[2 * p][0] = rl[0]; bl[2 * p][1] = rl[1];
                bl[2 * p + 1][0] = rl[2]; bl[2 * p + 1][1] = rl[3];
            }
#pragma unroll
            for (int mt = 0; mt < 4; ++mt)
#pragma unroll
                for (int nt = 0; nt < 4; ++nt) {
                    mma_f16_16n8k16(acc[mt][nt], ah[mt], bh[nt]);
                    mma_f16_16n8k16(acc[mt][nt], ah[mt], bl[nt]);
                    mma_f16_16n8k16(acc[mt][nt], al[mt], bh[nt]);
                }
        }
    }

    // ---- epilogue: bias + PReLU, float2 stores ----
    const float alv = alpha[0];
#pragma unroll
    for (int mt = 0; mt < 4; ++mt) {
        int r0 = bm + mwarp + mt * 16 + g;
#pragma unroll
        for (int nt = 0; nt < 4; ++nt) {
            int cb = bn + nwarp + nt * 8 + 2 * t4;
            float b0 = 0.f, b1 = 0.f;
            if (bias) { b0 = bias[cb]; b1 = bias[cb + 1]; }
            float v0 = acc[mt][nt][0] + b0;
            float v1 = acc[mt][nt][1] + b1;
            float v2 = acc[mt][nt][2] + b0;
            float v3 = acc[mt][nt][3] + b1;
            float2 o0, o1;
            o0.x = v0 >= 0.f ? v0 : alv * v0;
            o0.y = v1 >= 0.f ? v1 : alv * v1;
            o1.x = v2 >= 0.f ? v2 : alv * v2;
            o1.y = v3 >= 0.f ? v3 : alv * v3;
            *(float2*)&Y[(size_t)r0 * DD + cb]       = o0;
            *(float2*)&Y[(size_t)(r0 + 8) * DD + cb] = o1;
        }
    }
}

// ---------------- output matvec: angles = X @ Wo^T + bo ----------------
__global__ void matvec_kernel(const float* __restrict__ X,
                              const float* __restrict__ Wo,
                              const float* __restrict__ bo)
{
    int warp = (blockIdx.x * blockDim.x + threadIdx.x) >> 5;
    int lane = threadIdx.x & 31;
    if (warp >= NN) return;
    const float* x = X + (size_t)warp * DD;
    float s = 0.f;
#pragma unroll
    for (int it = 0; it < 4; ++it) {
        int k = (lane + it * 32) * 4;
        float4 xv = *(const float4*)&x[k];
        float4 wv = *(const float4*)&Wo[k];
        s = fmaf(xv.x, wv.x, s);
        s = fmaf(xv.y, wv.y, s);
        s = fmaf(xv.z, wv.z, s);
        s = fmaf(xv.w, wv.w, s);
    }
#pragma unroll
    for (int o = 16; o; o >>= 1) s += __shfl_xor_sync(0xffffffffu, s, o);
    if (lane == 0) g_angles[warp] = s + bo[0];
}

// ---------------- edge pass: build bit-adjacency + hop-1 segment sum ----
__global__ void edge_kernel(const int* __restrict__ ei, int E)
{
    int t = blockIdx.x * blockDim.x + threadIdx.x;
    if (t >= E) return;
    int s = ei[t];
    int d = ei[E + t];
    atomicOr(&g_A[s * NW + (d >> 5)], 1u << (d & 31));
    atomicAdd(&g_acc[s], g_angles[d]);   // duplicates count (raw edge list)
}

__global__ void a1_kernel()
{
    int i = blockIdx.x * blockDim.x + threadIdx.x;
    if (i < NN) g_a1[i] = g_angles[i] + 0.25f * g_acc[i];   // (0.5)^2
}

// ======================================================================
//  Hop kernels: serial-ffs row-OR (proven R2/R4 form) + coalesced
//  broadcast-masked gather through shared word buffer.
// ======================================================================
template <bool STORE_A2>
__device__ __forceinline__ void hop_body(
    const unsigned* __restrict__ nbrmat,   // rows to OR (g_A or g_A2)
    const float*    __restrict__ vec,      // vector to gather (g_a1 or g_a2)
    float scale, float* __restrict__ dst)  // output scalar array
{
    const int i = blockIdx.x;
    const int t = threadIdx.x;  // 0..127

    __shared__ unsigned srow[NW];
    __shared__ unsigned swords[NW];
    __shared__ float    red[NW];

    srow[t] = g_A[i * NW + t];
    __syncthreads();

    unsigned accw = 0u;
    for (int w = 0; w < NW; ++w) {
        unsigned bits = srow[w];
        while (bits) {
            int b = __ffs(bits) - 1;
            bits &= bits - 1;
            accw |= nbrmat[(w * 32 + b) * NW + t];
        }
    }
    if (STORE_A2) g_A2[i * NW + t] = accw;
    swords[t] = accw;
    __syncthreads();

    // coalesced gather: iteration k, thread t handles element k*128+t.
    // word index (4k + t/32) is warp-uniform -> smem broadcast.
    float p = 0.f;
#pragma unroll 4
    for (int k = 0; k < 32; ++k) {
        int idx = k * 128 + t;
        unsigned wrd = swords[idx >> 5];
        p += vec[idx] * (float)((wrd >> (idx & 31)) & 1u);
    }
    red[t] = p;
    __syncthreads();
#pragma unroll
    for (int s = 64; s; s >>= 1) {
        if (t < s) red[t] += red[t + s];
        __syncthreads();
    }
    if (t == 0) dst[i] = vec[i] + scale * red[0];
}

__global__ __launch_bounds__(128) void hop2_kernel()
{
    hop_body<true>(g_A, g_a1, 1.0f / 9.0f, g_a2);
}

__global__ __launch_bounds__(128) void hop3_kernel(float* __restrict__ out)
{
    hop_body<false>(g_A2, g_a2, 1.0f / 16.0f, out);
}

// ---------------------------- launch ------------------------------------
extern "C" void kernel_launch(void* const* d_in, const int* in_sizes, int n_in,
                              void* d_out, int out_size)
{
    const float* coeffs = (const float*)d_in[0];
    const int*   eidx   = (const int*)  d_in[1];
    const float* W0     = (const float*)d_in[2];
    const float* b0     = (const float*)d_in[3];
    const float* a0     = (const float*)d_in[4];
    const float* W1     = (const float*)d_in[5];
    const float* a1p    = (const float*)d_in[6];
    const float* W2     = (const float*)d_in[7];
    const float* a2p    = (const float*)d_in[8];
    const float* Wo     = (const float*)d_in[9];
    const float* bo     = (const float*)d_in[10];
    float* out = (float*)d_out;

    const int E = in_sizes[1] / 2;

    float *p_buf0, *p_buf1;
    cudaGetSymbolAddress((void**)&p_buf0, g_buf0);
    cudaGetSymbolAddress((void**)&p_buf1, g_buf1);

    cudaFuncSetAttribute(tc_gemm, cudaFuncAttributeMaxDynamicSharedMemorySize,
                         GEMM_SMEM);

    // 1) zero A bitmatrix + hop-1 accumulator
    zero_kernel<<<1024, 256>>>();

    // 2) MLP: 3 split-fp16 mma.sync GEMM+PReLU layers
    dim3 ggrid(DD / BN, NN / BM);   // (4, 32) = 128 CTAs
    tc_gemm<<<ggrid, 256, GEMM_SMEM>>>(coeffs, W0, b0,      a0,  p_buf1);
    tc_gemm<<<ggrid, 256, GEMM_SMEM>>>(p_buf1, W1, nullptr, a1p, p_buf0);
    tc_gemm<<<ggrid, 256, GEMM_SMEM>>>(p_buf0, W2, nullptr, a2p, p_buf1);

    // 3) output head -> angles
    matvec_kernel<<<(NN * 32 + 255) / 256, 256>>>(p_buf1, Wo, bo);

    // 4) edges: bit adjacency + hop-1 raw segment sum
    edge_kernel<<<(E + 255) / 256, 256>>>(eidx, E);
    a1_kernel<<<(NN + 255) / 256, 256>>>();

    // 5) hop 2 (materializes A2 bits) and hop 3 (fused, writes output)
    hop2_kernel<<<NN, 128>>>();
    hop3_kernel<<<NN, 128>>>(out);
}

// round 9
// speedup vs baseline: 2.6097x; 1.1958x over previous
#include <cuda_runtime.h>
#include <cuda_bf16.h>
#include <cuda_fp16.h>
#include <cstdint>

// Problem constants (fixed by the dataset)
#define NN 4096      // nodes
#define DD 512       // feature dim
#define NW 128       // bitmask words per row (4096/32)

// ---------------- device scratch (no allocation allowed) ----------------
__device__ float    g_buf1[NN * DD];          // fp32 layer-3 output
__device__ float    g_angles[NN];
__device__ float    g_acc[NN];
__device__ float    g_a1[NN];
__device__ float    g_a2[NN];
__device__ unsigned g_A [NN * NW];
__device__ unsigned g_A2[NN * NW];
// fp16 split buffers
__device__ __align__(16) __half g_xh[NN * DD];
__device__ __align__(16) __half g_xl[NN * DD];
__device__ __align__(16) __half g_yh[NN * DD];
__device__ __align__(16) __half g_yl[NN * DD];
__device__ __align__(16) __half g_wh[3 * DD * DD];
__device__ __align__(16) __half g_wl[3 * DD * DD];

// ---------------- zero scratch (deterministic per call) ----------------
__global__ void zero_kernel() {
    int idx = blockIdx.x * blockDim.x + threadIdx.x;
    int total = NN * NW;
    for (int i = idx; i < total; i += gridDim.x * blockDim.x) g_A[i] = 0u;
    if (idx < NN) g_acc[idx] = 0.0f;
}

// ---------------- fp32 -> (fp16 hi, fp16 lo) split ----------------------
__global__ void split_kernel(const float* __restrict__ src,
                             __half* __restrict__ h, __half* __restrict__ l,
                             int n)
{
    int idx = blockIdx.x * blockDim.x + threadIdx.x;
    int i = idx * 4;
    if (i >= n) return;
    float4 v = *(const float4*)(src + i);
    __half hx = __float2half_rn(v.x), hy = __float2half_rn(v.y);
    __half hz = __float2half_rn(v.z), hw = __float2half_rn(v.w);
    __half2 h01 = __halves2half2(hx, hy), h23 = __halves2half2(hz, hw);
    __half2 l01 = __halves2half2(__float2half_rn(v.x - __half2float(hx)),
                                 __float2half_rn(v.y - __half2float(hy)));
    __half2 l23 = __halves2half2(__float2half_rn(v.z - __half2float(hz)),
                                 __float2half_rn(v.w - __half2float(hw)));
    *(__half2*)(h + i)     = h01;
    *(__half2*)(h + i + 2) = h23;
    *(__half2*)(l + i)     = l01;
    *(__half2*)(l + i + 2) = l23;
}

// ======================================================================
//  3xFP16 split GEMM, cp.async 3-stage pipeline + ldmatrix + mma.sync:
//     Y = prelu(Xh@Wh^T + Xh@Wl^T + Xl@Wh^T + bias, alpha)
//  CTA: 128(M) x 128(N), 256 threads (8 warps 2x4), warp 64x32.
//  K chunks of 32; smem stage = {Ah,Al,Bh,Bl} 128x40 halves each.
// ======================================================================
#define BM 128
#define BN 128
#define BK 32
#define LDSH 40                     // padded row stride in halves
#define ARR_B  (128 * LDSH * 2)     // 10240 B per array
#define STAGE_B (4 * ARR_B)         // 40960 B per stage
#define NSTAGE 3
#define GEMM_SMEM (NSTAGE * STAGE_B)
#define NCH (DD / BK)               // 16

__device__ __forceinline__ void mma_f16_16n8k16(
    float c[4], const uint32_t a[4], const uint32_t b[2])
{
    asm volatile(
        "mma.sync.aligned.m16n8k16.row.col.f32.f16.f16.f32 "
        "{%0,%1,%2,%3}, {%4,%5,%6,%7}, {%8,%9}, {%0,%1,%2,%3};"
        : "+f"(c[0]), "+f"(c[1]), "+f"(c[2]), "+f"(c[3])
        : "r"(a[0]), "r"(a[1]), "r"(a[2]), "r"(a[3]),
          "r"(b[0]), "r"(b[1]));
}

__device__ __forceinline__ void ldsm_x4(uint32_t r[4], uint32_t addr) {
    asm volatile(
        "ldmatrix.sync.aligned.m8n8.x4.shared.b16 {%0,%1,%2,%3}, [%4];"
        : "=r"(r[0]), "=r"(r[1]), "=r"(r[2]), "=r"(r[3]) : "r"(addr));
}

__device__ __forceinline__ void cpa16(uint32_t dst, const void* src) {
    asm volatile("cp.async.cg.shared.global [%0], [%1], 16;"
                 :: "r"(dst), "l"(src) : "memory");
}

template <bool SPLIT_OUT>
__global__ __launch_bounds__(256, 1) void tc_gemm(
    const __half* __restrict__ Xh, const __half* __restrict__ Xl,
    const __half* __restrict__ Wh, const __half* __restrict__ Wl,
    const float* __restrict__ bias, const float* __restrict__ alpha,
    float* __restrict__ Yf, __half* __restrict__ Yh, __half* __restrict__ Yl)
{
    extern __shared__ char sm[];

    const int tid  = threadIdx.x;
    const int lane = tid & 31;
    const int wid  = tid >> 5;
    const int g    = lane >> 2;
    const int t4   = lane & 3;
    const int mwarp = (wid >> 2) * 64;
    const int nwarp = (wid & 3) * 32;
    const int bm = blockIdx.y * BM;
    const int bn = blockIdx.x * BN;

    // cp.async mapping: per array, 512 x 16B ops; thread does rows crow, crow+64
    const int crow = tid >> 2;      // 0..63
    const int cq   = tid & 3;       // 16B unit within 64B row chunk

    // ldmatrix per-lane offsets (halves)
    const int rowA = lane & 15;
    const int kofA = (lane & 16) ? 8 : 0;
    const int rowB = (lane & 7) + ((lane & 16) ? 8 : 0);
    const int kofB = (lane & 8) ? 8 : 0;

    const uint32_t smbase = (uint32_t)__cvta_generic_to_shared(sm);

    float acc[4][4][4];
#pragma unroll
    for (int i = 0; i < 4; ++i)
#pragma unroll
        for (int j = 0; j < 4; ++j)
#pragma unroll
            for (int q = 0; q < 4; ++q) acc[i][j][q] = 0.0f;

    // ---- issue helper (macro-ish lambda) ----
    auto issue = [&](int kc) {
        const uint32_t st = smbase + (uint32_t)(kc % NSTAGE) * STAGE_B;
#pragma unroll
        for (int i = 0; i < 2; ++i) {
            int r = crow + i * 64;
            uint32_t so = (uint32_t)(r * (LDSH * 2) + cq * 16);
            size_t goA = (size_t)(bm + r) * DD + kc * BK + cq * 8;
            size_t goB = (size_t)(bn + r) * DD + kc * BK + cq * 8;
            cpa16(st + 0 * ARR_B + so, Xh + goA);
            cpa16(st + 1 * ARR_B + so, Xl + goA);
            cpa16(st + 2 * ARR_B + so, Wh + goB);
            cpa16(st + 3 * ARR_B + so, Wl + goB);
        }
        asm volatile("cp.async.commit_group;" ::: "memory");
    };

    issue(0);
    issue(1);

    for (int kc = 0; kc < NCH; ++kc) {
        if (kc < NCH - 1)
            asm volatile("cp.async.wait_group 1;" ::: "memory");
        else
            asm volatile("cp.async.wait_group 0;" ::: "memory");
        __syncthreads();
        if (kc + 2 < NCH) issue(kc + 2);

        const uint32_t st  = smbase + (uint32_t)(kc % NSTAGE) * STAGE_B;
        const uint32_t AhU = st;
        const uint32_t AlU = st + ARR_B;
        const uint32_t BhU = st + 2 * ARR_B;
        const uint32_t BlU = st + 3 * ARR_B;

#pragma unroll
        for (int ks = 0; ks < 2; ++ks) {
            uint32_t ah[4][4], al[4][4], bh[4][2], bl[4][2];
            const uint32_t aoff = (uint32_t)(rowA * LDSH + ks * 16 + kofA) * 2u;
            const uint32_t boff = (uint32_t)(rowB * LDSH + ks * 16 + kofB) * 2u;
#pragma unroll
            for (int mt = 0; mt < 4; ++mt) {
                uint32_t mb = (uint32_t)((mwarp + mt * 16) * LDSH) * 2u;
                ldsm_x4(ah[mt], AhU + mb + aoff);
                ldsm_x4(al[mt], AlU + mb + aoff);
            }
#pragma unroll
            for (int p = 0; p < 2; ++p) {
                uint32_t nb = (uint32_t)((nwarp + p * 16) * LDSH) * 2u;
                uint32_t rh[4], rl[4];
                ldsm_x4(rh, BhU + nb + boff);
                ldsm_x4(rl, BlU + nb + boff);
                bh[2 * p][0] = rh[0]; bh[2 * p][1] = rh[1];
                bh[2 * p + 1][0] = rh[2]; bh[2 * p + 1][1] = rh[3];
                bl[2 * p][0] = rl[0]; bl[2 * p][1] = rl[1];
                bl[2 * p + 1][0] = rl[2]; bl[2 * p + 1][1] = rl[3];
            }
#pragma unroll
            for (int mt = 0; mt < 4; ++mt)
#pragma unroll
                for (int nt = 0; nt < 4; ++nt) {
                    mma_f16_16n8k16(acc[mt][nt], ah[mt], bh[nt]);
                    mma_f16_16n8k16(acc[mt][nt], ah[mt], bl[nt]);
                    mma_f16_16n8k16(acc[mt][nt], al[mt], bh[nt]);
                }
        }
    }

    // ---- epilogue: bias + PReLU; fp32 store or split fp16 store ----
    const float alv = alpha[0];
#pragma unroll
    for (int mt = 0; mt < 4; ++mt) {
        int r0 = bm + mwarp + mt * 16 + g;
#pragma unroll
        for (int nt = 0; nt < 4; ++nt) {
            int cb = bn + nwarp + nt * 8 + 2 * t4;
            float b0 = 0.f, b1 = 0.f;
            if (bias) { b0 = bias[cb]; b1 = bias[cb + 1]; }
            float v0 = acc[mt][nt][0] + b0;
            float v1 = acc[mt][nt][1] + b1;
            float v2 = acc[mt][nt][2] + b0;
            float v3 = acc[mt][nt][3] + b1;
            v0 = v0 >= 0.f ? v0 : alv * v0;
            v1 = v1 >= 0.f ? v1 : alv * v1;
            v2 = v2 >= 0.f ? v2 : alv * v2;
            v3 = v3 >= 0.f ? v3 : alv * v3;
            if (SPLIT_OUT) {
                __half h0 = __float2half_rn(v0), h1 = __float2half_rn(v1);
                __half h2 = __float2half_rn(v2), h3 = __float2half_rn(v3);
                __half2 lo01 = __halves2half2(__float2half_rn(v0 - __half2float(h0)),
                                              __float2half_rn(v1 - __half2float(h1)));
                __half2 lo23 = __halves2half2(__float2half_rn(v2 - __half2float(h2)),
                                              __float2half_rn(v3 - __half2float(h3)));
                *(__half2*)&Yh[(size_t)r0 * DD + cb]       = __halves2half2(h0, h1);
                *(__half2*)&Yl[(size_t)r0 * DD + cb]       = lo01;
                *(__half2*)&Yh[(size_t)(r0 + 8) * DD + cb] = __halves2half2(h2, h3);
                *(__half2*)&Yl[(size_t)(r0 + 8) * DD + cb] = lo23;
            } else {
                float2 o0 = make_float2(v0, v1);
                float2 o1 = make_float2(v2, v3);
                *(float2*)&Yf[(size_t)r0 * DD + cb]       = o0;
                *(float2*)&Yf[(size_t)(r0 + 8) * DD + cb] = o1;
            }
        }
    }
}

// ---------------- output matvec: angles = X @ Wo^T + bo ----------------
__global__ void matvec_kernel(const float* __restrict__ X,
                              const float* __restrict__ Wo,
                              const float* __restrict__ bo)
{
    int warp = (blockIdx.x * blockDim.x + threadIdx.x) >> 5;
    int lane = threadIdx.x & 31;
    if (warp >= NN) return;
    const float* x = X + (size_t)warp * DD;
    float s = 0.f;
#pragma unroll
    for (int it = 0; it < 4; ++it) {
        int k = (lane + it * 32) * 4;
        float4 xv = *(const float4*)&x[k];
        float4 wv = *(const float4*)&Wo[k];
        s = fmaf(xv.x, wv.x, s);
        s = fmaf(xv.y, wv.y, s);
        s = fmaf(xv.z, wv.z, s);
        s = fmaf(xv.w, wv.w, s);
    }
#pragma unroll
    for (int o = 16; o; o >>= 1) s += __shfl_xor_sync(0xffffffffu, s, o);
    if (lane == 0) g_angles[warp] = s + bo[0];
}

// ---------------- edge pass: build bit-adjacency + hop-1 segment sum ----
__global__ void edge_kernel(const int* __restrict__ ei, int E)
{
    int t = blockIdx.x * blockDim.x + threadIdx.x;
    if (t >= E) return;
    int s = ei[t];
    int d = ei[E + t];
    atomicOr(&g_A[s * NW + (d >> 5)], 1u << (d & 31));
    atomicAdd(&g_acc[s], g_angles[d]);   // duplicates count (raw edge list)
}

__global__ void a1_kernel()
{
    int i = blockIdx.x * blockDim.x + threadIdx.x;
    if (i < NN) g_a1[i] = g_angles[i] + 0.25f * g_acc[i];   // (0.5)^2
}

// ======================================================================
//  Hop kernels: prefix-sum neighbor extraction + 4-way unrolled row-OR
//  + coalesced broadcast-masked gather.
// ======================================================================
#define NBR_CAP 4096

template <bool STORE_A2>
__device__ __forceinline__ void hop_body(
    const unsigned* __restrict__ nbrmat,
    const float*    __restrict__ vec,
    float scale, float* __restrict__ dst)
{
    const int i = blockIdx.x;
    const int t = threadIdx.x;  // 0..127

    __shared__ unsigned short s_nbr[NBR_CAP];
    __shared__ int   s_wtot[4];
    __shared__ int   s_deg;
    __shared__ unsigned swords[NW];
    __shared__ float red[NW];

    // --- extract this row's neighbor list (deterministic order) ---
    unsigned mybits = g_A[i * NW + t];
    int cnt = __popc(mybits);
    int incl = cnt;
#pragma unroll
    for (int o = 1; o < 32; o <<= 1) {
        int v = __shfl_up_sync(0xffffffffu, incl, o);
        if ((t & 31) >= o) incl += v;
    }
    if ((t & 31) == 31) s_wtot[t >> 5] = incl;
    __syncthreads();
    int base = incl - cnt;
#pragma unroll
    for (int w = 0; w < 4; ++w)
        if (w < (t >> 5)) base += s_wtot[w];
    int pos = base;
    unsigned bb = mybits;
    while (bb) {
        int b = __ffs(bb) - 1;
        bb &= bb - 1;
        s_nbr[pos++] = (unsigned short)(t * 32 + b);
    }
    if (t == 127) s_deg = base + cnt;
    __syncthreads();
    const int deg = s_deg;

    // --- OR neighbor rows (word t), 4-way ILP ---
    unsigned accw = 0u;
    int j = 0;
    for (; j + 4 <= deg; j += 4) {
        int n0 = s_nbr[j], n1 = s_nbr[j + 1], n2 = s_nbr[j + 2], n3 = s_nbr[j + 3];
        unsigned v0 = nbrmat[n0 * NW + t];
        unsigned v1 = nbrmat[n1 * NW + t];
        unsigned v2 = nbrmat[n2 * NW + t];
        unsigned v3 = nbrmat[n3 * NW + t];
        accw |= (v0 | v1) | (v2 | v3);
    }
    for (; j < deg; ++j) accw |= nbrmat[s_nbr[j] * NW + t];

    if (STORE_A2) g_A2[i * NW + t] = accw;
    swords[t] = accw;
    __syncthreads();

    // --- coalesced masked gather: element k*128+t, warp-uniform word ---
    float p = 0.f;
#pragma unroll 4
    for (int k = 0; k < 32; ++k) {
        int idx = k * 128 + t;
        unsigned wrd = swords[idx >> 5];
        p += vec[idx] * (float)((wrd >> (idx & 31)) & 1u);
    }
    red[t] = p;
    __syncthreads();
#pragma unroll
    for (int s = 64; s; s >>= 1) {
        if (t < s) red[t] += red[t + s];
        __syncthreads();
    }
    if (t == 0) dst[i] = vec[i] + scale * red[0];
}

__global__ __launch_bounds__(128) void hop2_kernel()
{
    hop_body<true>(g_A, g_a1, 1.0f / 9.0f, g_a2);
}

__global__ __launch_bounds__(128) void hop3_kernel(float* __restrict__ out)
{
    hop_body<false>(g_A2, g_a2, 1.0f / 16.0f, out);
}

// ---------------------------- launch ------------------------------------
extern "C" void kernel_launch(void* const* d_in, const int* in_sizes, int n_in,
                              void* d_out, int out_size)
{
    const float* coeffs = (const float*)d_in[0];
    const int*   eidx   = (const int*)  d_in[1];
    const float* W0     = (const float*)d_in[2];
    const float* b0     = (const float*)d_in[3];
    const float* a0     = (const float*)d_in[4];
    const float* W1     = (const float*)d_in[5];
    const float* a1p    = (const float*)d_in[6];
    const float* W2     = (const float*)d_in[7];
    const float* a2p    = (const float*)d_in[8];
    const float* Wo     = (const float*)d_in[9];
    const float* bo     = (const float*)d_in[10];
    float* out = (float*)d_out;

    const int E = in_sizes[1] / 2;

    float *p_buf1;
    __half *p_xh, *p_xl, *p_yh, *p_yl, *p_wh, *p_wl;
    cudaGetSymbolAddress((void**)&p_buf1, g_buf1);
    cudaGetSymbolAddress((void**)&p_xh, g_xh);
    cudaGetSymbolAddress((void**)&p_xl, g_xl);
    cudaGetSymbolAddress((void**)&p_yh, g_yh);
    cudaGetSymbolAddress((void**)&p_yl, g_yl);
    cudaGetSymbolAddress((void**)&p_wh, g_wh);
    cudaGetSymbolAddress((void**)&p_wl, g_wl);

    cudaFuncSetAttribute(tc_gemm<true>,  cudaFuncAttributeMaxDynamicSharedMemorySize, GEMM_SMEM);
    cudaFuncSetAttribute(tc_gemm<false>, cudaFuncAttributeMaxDynamicSharedMemorySize, GEMM_SMEM);

    // 1) zero A bitmatrix + hop-1 accumulator
    zero_kernel<<<1024, 256>>>();

    // 2) pre-split coeffs and weights to fp16 hi/lo
    split_kernel<<<(NN * DD / 4 + 255) / 256, 256>>>(coeffs, p_xh, p_xl, NN * DD);
    split_kernel<<<(DD * DD / 4 + 255) / 256, 256>>>(W0, p_wh + 0 * DD * DD, p_wl + 0 * DD * DD, DD * DD);
    split_kernel<<<(DD * DD / 4 + 255) / 256, 256>>>(W1, p_wh + 1 * DD * DD, p_wl + 1 * DD * DD, DD * DD);
    split_kernel<<<(DD * DD / 4 + 255) / 256, 256>>>(W2, p_wh + 2 * DD * DD, p_wl + 2 * DD * DD, DD * DD);

    // 3) MLP: 3 split-fp16 GEMM+PReLU layers (cp.async pipeline)
    dim3 ggrid(DD / BN, NN / BM);   // (4, 32) = 128 CTAs
    tc_gemm<true ><<<ggrid, 256, GEMM_SMEM>>>(p_xh, p_xl, p_wh + 0 * DD * DD, p_wl + 0 * DD * DD,
                                              b0,      a0,  nullptr, p_yh, p_yl);
    tc_gemm<true ><<<ggrid, 256, GEMM_SMEM>>>(p_yh, p_yl, p_wh + 1 * DD * DD, p_wl + 1 * DD * DD,
                                              nullptr, a1p, nullptr, p_xh, p_xl);
    tc_gemm<false><<<ggrid, 256, GEMM_SMEM>>>(p_xh, p_xl, p_wh + 2 * DD * DD, p_wl + 2 * DD * DD,
                                              nullptr, a2p, p_buf1, nullptr, nullptr);

    // 4) output head -> angles
    matvec_kernel<<<(NN * 32 + 255) / 256, 256>>>(p_buf1, Wo, bo);

    // 5) edges: bit adjacency + hop-1 raw segment sum
    edge_kernel<<<(E + 255) / 256, 256>>>(eidx, E);
    a1_kernel<<<(NN + 255) / 256, 256>>>();

    // 6) hop 2 (materializes A2 bits) and hop 3 (fused, writes output)
    hop2_kernel<<<NN, 128>>>();
    hop3_kernel<<<NN, 128>>>(out);
}

// round 11
// speedup vs baseline: 2.6942x; 1.0324x over previous
#include <cuda_runtime.h>
#include <cuda_bf16.h>
#include <cuda_fp16.h>
#include <cstdint>

// Problem constants (fixed by the dataset)
#define NN 4096      // nodes
#define DD 512       // feature dim
#define NW 128       // bitmask words per row (4096/32)

// ---------------- device scratch (no allocation allowed) ----------------
__device__ float    g_angles[NN];
__device__ float    g_acc[NN];
__device__ float    g_a1[NN];
__device__ float    g_a2[NN];
__device__ unsigned g_A [NN * NW];
__device__ unsigned g_A2[NN * NW];
// fp16 split buffers
__device__ __align__(16) __half g_xh[NN * DD];
__device__ __align__(16) __half g_xl[NN * DD];
__device__ __align__(16) __half g_yh[NN * DD];
__device__ __align__(16) __half g_yl[NN * DD];
__device__ __align__(16) __half g_wh[3 * DD * DD];
__device__ __align__(16) __half g_wl[3 * DD * DD];

// ---------------- zero scratch (deterministic per call) ----------------
__global__ void zero_kernel() {
    int idx = blockIdx.x * blockDim.x + threadIdx.x;
    int total = NN * NW;
    for (int i = idx; i < total; i += gridDim.x * blockDim.x) g_A[i] = 0u;
    if (idx < NN) { g_acc[idx] = 0.0f; g_angles[idx] = 0.0f; }
}

// ---------------- fp32 -> (fp16 hi, fp16 lo) split ----------------------
__device__ __forceinline__ void split_store(const float* __restrict__ src,
                                            __half* __restrict__ h,
                                            __half* __restrict__ l, int i)
{
    float4 v = *(const float4*)(src + i);
    __half hx = __float2half_rn(v.x), hy = __float2half_rn(v.y);
    __half hz = __float2half_rn(v.z), hw = __float2half_rn(v.w);
    __half2 h01 = __halves2half2(hx, hy), h23 = __halves2half2(hz, hw);
    __half2 l01 = __halves2half2(__float2half_rn(v.x - __half2float(hx)),
                                 __float2half_rn(v.y - __half2float(hy)));
    __half2 l23 = __halves2half2(__float2half_rn(v.z - __half2float(hz)),
                                 __float2half_rn(v.w - __half2float(hw)));
    *(__half2*)(h + i)     = h01;
    *(__half2*)(h + i + 2) = h23;
    *(__half2*)(l + i)     = l01;
    *(__half2*)(l + i + 2) = l23;
}

__global__ void split_kernel(const float* __restrict__ src,
                             __half* __restrict__ h, __half* __restrict__ l,
                             int n)
{
    int idx = blockIdx.x * blockDim.x + threadIdx.x;
    int i = idx * 4;
    if (i >= n) return;
    split_store(src, h, l, i);
}

// merged 3-weight split (W0, W1, W2 -> g_wh/g_wl slabs)
__global__ void splitw_kernel(const float* __restrict__ W0,
                              const float* __restrict__ W1,
                              const float* __restrict__ W2,
                              __half* __restrict__ h, __half* __restrict__ l)
{
    const int per = DD * DD / 4;
    int idx = blockIdx.x * blockDim.x + threadIdx.x;
    if (idx >= 3 * per) return;
    int arr = idx / per;
    int i = (idx - arr * per) * 4;
    const float* src = arr == 0 ? W0 : (arr == 1 ? W1 : W2);
    split_store(src, h + arr * DD * DD, l + arr * DD * DD, i);
}

// ======================================================================
//  3xFP16 split GEMM, cp.async 3-stage pipeline + ldmatrix + mma.sync:
//     Y = prelu(Xh@Wh^T + Xh@Wl^T + Xl@Wh^T + bias, alpha)
//  MODE 1: store Y as split fp16 pair. MODE 2: fused output head --
//          atomicAdd per-row partials of Y @ Wo^T into g_angles.
//  CTA: 128(M) x 128(N), 256 threads (8 warps 2x4), warp 64x32.
// ======================================================================
#define BM 128
#define BN 128
#define BK 32
#define LDSH 40                     // padded row stride in halves
#define ARR_B  (128 * LDSH * 2)     // 10240 B per array
#define STAGE_B (4 * ARR_B)         // 40960 B per stage
#define NSTAGE 3
#define GEMM_SMEM (NSTAGE * STAGE_B)
#define NCH (DD / BK)               // 16

__device__ __forceinline__ void mma_f16_16n8k16(
    float c[4], const uint32_t a[4], const uint32_t b[2])
{
    asm volatile(
        "mma.sync.aligned.m16n8k16.row.col.f32.f16.f16.f32 "
        "{%0,%1,%2,%3}, {%4,%5,%6,%7}, {%8,%9}, {%0,%1,%2,%3};"
        : "+f"(c[0]), "+f"(c[1]), "+f"(c[2]), "+f"(c[3])
        : "r"(a[0]), "r"(a[1]), "r"(a[2]), "r"(a[3]),
          "r"(b[0]), "r"(b[1]));
}

__device__ __forceinline__ void ldsm_x4(uint32_t r[4], uint32_t addr) {
    asm volatile(
        "ldmatrix.sync.aligned.m8n8.x4.shared.b16 {%0,%1,%2,%3}, [%4];"
        : "=r"(r[0]), "=r"(r[1]), "=r"(r[2]), "=r"(r[3]) : "r"(addr));
}

__device__ __forceinline__ void cpa16(uint32_t dst, const void* src) {
    asm volatile("cp.async.cg.shared.global [%0], [%1], 16;"
                 :: "r"(dst), "l"(src) : "memory");
}

template <int MODE>
__global__ __launch_bounds__(256, 1) void tc_gemm(
    const __half* __restrict__ Xh, const __half* __restrict__ Xl,
    const __half* __restrict__ Wh, const __half* __restrict__ Wl,
    const float* __restrict__ bias, const float* __restrict__ alpha,
    const float* __restrict__ Wo,
    __half* __restrict__ Yh, __half* __restrict__ Yl)
{
    extern __shared__ char sm[];

    const int tid  = threadIdx.x;
    const int lane = tid & 31;
    const int wid  = tid >> 5;
    const int g    = lane >> 2;
    const int t4   = lane & 3;
    const int mwarp = (wid >> 2) * 64;
    const int nwarp = (wid & 3) * 32;
    const int bm = blockIdx.y * BM;
    const int bn = blockIdx.x * BN;

    const int crow = tid >> 2;      // 0..63
    const int cq   = tid & 3;       // 16B unit within 64B row chunk

    const int rowA = lane & 15;
    const int kofA = (lane & 16) ? 8 : 0;
    const int rowB = (lane & 7) + ((lane & 16) ? 8 : 0);
    const int kofB = (lane & 8) ? 8 : 0;

    const uint32_t smbase = (uint32_t)__cvta_generic_to_shared(sm);

    float acc[4][4][4];
#pragma unroll
    for (int i = 0; i < 4; ++i)
#pragma unroll
        for (int j = 0; j < 4; ++j)
#pragma unroll
            for (int q = 0; q < 4; ++q) acc[i][j][q] = 0.0f;

    auto issue = [&](int kc) {
        const uint32_t st = smbase + (uint32_t)(kc % NSTAGE) * STAGE_B;
#pragma unroll
        for (int i = 0; i < 2; ++i) {
            int r = crow + i * 64;
            uint32_t so = (uint32_t)(r * (LDSH * 2) + cq * 16);
            size_t goA = (size_t)(bm + r) * DD + kc * BK + cq * 8;
            size_t goB = (size_t)(bn + r) * DD + kc * BK + cq * 8;
            cpa16(st + 0 * ARR_B + so, Xh + goA);
            cpa16(st + 1 * ARR_B + so, Xl + goA);
            cpa16(st + 2 * ARR_B + so, Wh + goB);
            cpa16(st + 3 * ARR_B + so, Wl + goB);
        }
        asm volatile("cp.async.commit_group;" ::: "memory");
    };

    issue(0);
    issue(1);

    for (int kc = 0; kc < NCH; ++kc) {
        if (kc < NCH - 1)
            asm volatile("cp.async.wait_group 1;" ::: "memory");
        else
            asm volatile("cp.async.wait_group 0;" ::: "memory");
        __syncthreads();
        if (kc + 2 < NCH) issue(kc + 2);

        const uint32_t st  = smbase + (uint32_t)(kc % NSTAGE) * STAGE_B;
        const uint32_t AhU = st;
        const uint32_t AlU = st + ARR_B;
        const uint32_t BhU = st + 2 * ARR_B;
        const uint32_t BlU = st + 3 * ARR_B;

#pragma unroll
        for (int ks = 0; ks < 2; ++ks) {
            uint32_t ah[4][4], al[4][4], bh[4][2], bl[4][2];
            const uint32_t aoff = (uint32_t)(rowA * LDSH + ks * 16 + kofA) * 2u;
            const uint32_t boff = (uint32_t)(rowB * LDSH + ks * 16 + kofB) * 2u;
#pragma unroll
            for (int mt = 0; mt < 4; ++mt) {
                uint32_t mb = (uint32_t)((mwarp + mt * 16) * LDSH) * 2u;
                ldsm_x4(ah[mt], AhU + mb + aoff);
                ldsm_x4(al[mt], AlU + mb + aoff);
            }
#pragma unroll
            for (int p = 0; p < 2; ++p) {
                uint32_t nb = (uint32_t)((nwarp + p * 16) * LDSH) * 2u;
                uint32_t rh[4], rl[4];
                ldsm_x4(rh, BhU + nb + boff);
                ldsm_x4(rl, BlU + nb + boff);
                bh[2 * p][0] = rh[0]; bh[2 * p][1] = rh[1];
                bh[2 * p + 1][0] = rh[2]; bh[2 * p + 1][1] = rh[3];
                bl[2 * p][0] = rl[0]; bl[2 * p][1] = rl[1];
                bl[2 * p + 1][0] = rl[2]; bl[2 * p + 1][1] = rl[3];
            }
#pragma unroll
            for (int mt = 0; mt < 4; ++mt)
#pragma unroll
                for (int nt = 0; nt < 4; ++nt) {
                    mma_f16_16n8k16(acc[mt][nt], ah[mt], bh[nt]);
                    mma_f16_16n8k16(acc[mt][nt], ah[mt], bl[nt]);
                    mma_f16_16n8k16(acc[mt][nt], al[mt], bh[nt]);
                }
        }
    }

    // ---- epilogue ----
    const float alv = alpha[0];
#pragma unroll
    for (int mt = 0; mt < 4; ++mt) {
        int r0 = bm + mwarp + mt * 16 + g;
        float p0 = 0.f, p1 = 0.f;
#pragma unroll
        for (int nt = 0; nt < 4; ++nt) {
            int cb = bn + nwarp + nt * 8 + 2 * t4;
            float b0 = 0.f, b1 = 0.f;
            if (bias) { b0 = bias[cb]; b1 = bias[cb + 1]; }
            float v0 = acc[mt][nt][0] + b0;
            float v1 = acc[mt][nt][1] + b1;
            float v2 = acc[mt][nt][2] + b0;
            float v3 = acc[mt][nt][3] + b1;
            v0 = v0 >= 0.f ? v0 : alv * v0;
            v1 = v1 >= 0.f ? v1 : alv * v1;
            v2 = v2 >= 0.f ? v2 : alv * v2;
            v3 = v3 >= 0.f ? v3 : alv * v3;
            if (MODE == 1) {
                __half h0 = __float2half_rn(v0), h1 = __float2half_rn(v1);
                __half h2 = __float2half_rn(v2), h3 = __float2half_rn(v3);
                __half2 lo01 = __halves2half2(__float2half_rn(v0 - __half2float(h0)),
                                              __float2half_rn(v1 - __half2float(h1)));
                __half2 lo23 = __halves2half2(__float2half_rn(v2 - __half2float(h2)),
                                              __float2half_rn(v3 - __half2float(h3)));
                *(__half2*)&Yh[(size_t)r0 * DD + cb]       = __halves2half2(h0, h1);
                *(__half2*)&Yl[(size_t)r0 * DD + cb]       = lo01;
                *(__half2*)&Yh[(size_t)(r0 + 8) * DD + cb] = __halves2half2(h2, h3);
                *(__half2*)&Yl[(size_t)(r0 + 8) * DD + cb] = lo23;
            } else {
                // fused output head: partial dot with Wo over this tile's cols
                float w0 = Wo[cb], w1 = Wo[cb + 1];
                p0 = fmaf(v0, w0, fmaf(v1, w1, p0));
                p1 = fmaf(v2, w0, fmaf(v3, w1, p1));
            }
        }
        if (MODE == 2) {
            p0 += __shfl_xor_sync(0xffffffffu, p0, 1);
            p0 += __shfl_xor_sync(0xffffffffu, p0, 2);
            p1 += __shfl_xor_sync(0xffffffffu, p1, 1);
            p1 += __shfl_xor_sync(0xffffffffu, p1, 2);
            if (t4 == 0) {
                atomicAdd(&g_angles[r0],     p0);
                atomicAdd(&g_angles[r0 + 8], p1);
            }
        }
    }
}

// ---------------- edge pass: build bit-adjacency + hop-1 segment sum ----
// angles_full(d) = g_angles[d] + bo  (bo folded in here)
__global__ void edge_kernel(const int* __restrict__ ei, int E,
                            const float* __restrict__ bo)
{
    int t = blockIdx.x * blockDim.x + threadIdx.x;
    if (t >= E) return;
    int s = ei[t];
    int d = ei[E + t];
    atomicOr(&g_A[s * NW + (d >> 5)], 1u << (d & 31));
    atomicAdd(&g_acc[s], g_angles[d] + bo[0]);   // duplicates count
}

__global__ void a1_kernel(const float* __restrict__ bo)
{
    int i = blockIdx.x * blockDim.x + threadIdx.x;
    if (i < NN) g_a1[i] = (g_angles[i] + bo[0]) + 0.25f * g_acc[i];  // (0.5)^2
}

// ======================================================================
//  Hop kernels: prefix-sum neighbor extraction + 8-way unrolled row-OR
//  + coalesced broadcast-masked gather.
// ======================================================================
#define NBR_CAP 4096

template <bool STORE_A2>
__device__ __forceinline__ void hop_body(
    const unsigned* __restrict__ nbrmat,
    const float*    __restrict__ vec,
    float scale, float* __restrict__ dst)
{
    const int i = blockIdx.x;
    const int t = threadIdx.x;  // 0..127

    __shared__ unsigned short s_nbr[NBR_CAP];
    __shared__ int   s_wtot[4];
    __shared__ int   s_deg;
    __shared__ unsigned swords[NW];
    __shared__ float red[NW];

    // --- extract this row's neighbor list (deterministic order) ---
    unsigned mybits = g_A[i * NW + t];
    int cnt = __popc(mybits);
    int incl = cnt;
#pragma unroll
    for (int o = 1; o < 32; o <<= 1) {
        int v = __shfl_up_sync(0xffffffffu, incl, o);
        if ((t & 31) >= o) incl += v;
    }
    if ((t & 31) == 31) s_wtot[t >> 5] = incl;
    __syncthreads();
    int base = incl - cnt;
#pragma unroll
    for (int w = 0; w < 4; ++w)
        if (w < (t >> 5)) base += s_wtot[w];
    int pos = base;
    unsigned bb = mybits;
    while (bb) {
        int b = __ffs(bb) - 1;
        bb &= bb - 1;
        s_nbr[pos++] = (unsigned short)(t * 32 + b);
    }
    if (t == 127) s_deg = base + cnt;
    __syncthreads();
    const int deg = s_deg;

    // --- OR neighbor rows (word t), 8-way ILP ---
    unsigned accw = 0u;
    int j = 0;
    for (; j + 8 <= deg; j += 8) {
        unsigned v0 = nbrmat[s_nbr[j]     * NW + t];
        unsigned v1 = nbrmat[s_nbr[j + 1] * NW + t];
        unsigned v2 = nbrmat[s_nbr[j + 2] * NW + t];
        unsigned v3 = nbrmat[s_nbr[j + 3] * NW + t];
        unsigned v4 = nbrmat[s_nbr[j + 4] * NW + t];
        unsigned v5 = nbrmat[s_nbr[j + 5] * NW + t];
        unsigned v6 = nbrmat[s_nbr[j + 6] * NW + t];
        unsigned v7 = nbrmat[s_nbr[j + 7] * NW + t];
        accw |= ((v0 | v1) | (v2 | v3)) | ((v4 | v5) | (v6 | v7));
    }
    for (; j < deg; ++j) accw |= nbrmat[s_nbr[j] * NW + t];

    if (STORE_A2) g_A2[i * NW + t] = accw;
    swords[t] = accw;
    __syncthreads();

    // --- coalesced masked gather: element k*128+t, warp-uniform word ---
    float p = 0.f;
#pragma unroll 4
    for (int k = 0; k < 32; ++k) {
        int idx = k * 128 + t;
        unsigned wrd = swords[idx >> 5];
        p += vec[idx] * (float)((wrd >> (idx & 31)) & 1u);
    }
    red[t] = p;
    __syncthreads();
#pragma unroll
    for (int s = 64; s; s >>= 1) {
        if (t < s) red[t] += red[t + s];
        __syncthreads();
    }
    if (t == 0) dst[i] = vec[i] + scale * red[0];
}

__global__ __launch_bounds__(128) void hop2_kernel()
{
    hop_body<true>(g_A, g_a1, 1.0f / 9.0f, g_a2);
}

__global__ __launch_bounds__(128) void hop3_kernel(float* __restrict__ out)
{
    hop_body<false>(g_A2, g_a2, 1.0f / 16.0f, out);
}

// ---------------------------- launch ------------------------------------
extern "C" void kernel_launch(void* const* d_in, const int* in_sizes, int n_in,
                              void* d_out, int out_size)
{
    const float* coeffs = (const float*)d_in[0];
    const int*   eidx   = (const int*)  d_in[1];
    const float* W0     = (const float*)d_in[2];
    const float* b0     = (const float*)d_in[3];
    const float* a0     = (const float*)d_in[4];
    const float* W1     = (const float*)d_in[5];
    const float* a1p    = (const float*)d_in[6];
    const float* W2     = (const float*)d_in[7];
    const float* a2p    = (const float*)d_in[8];
    const float* Wo     = (const float*)d_in[9];
    const float* bo     = (const float*)d_in[10];
    float* out = (float*)d_out;

    const int E = in_sizes[1] / 2;

    __half *p_xh, *p_xl, *p_yh, *p_yl, *p_wh, *p_wl;
    cudaGetSymbolAddress((void**)&p_xh, g_xh);
    cudaGetSymbolAddress((void**)&p_xl, g_xl);
    cudaGetSymbolAddress((void**)&p_yh, g_yh);
    cudaGetSymbolAddress((void**)&p_yl, g_yl);
    cudaGetSymbolAddress((void**)&p_wh, g_wh);
    cudaGetSymbolAddress((void**)&p_wl, g_wl);

    cudaFuncSetAttribute(tc_gemm<1>, cudaFuncAttributeMaxDynamicSharedMemorySize, GEMM_SMEM);
    cudaFuncSetAttribute(tc_gemm<2>, cudaFuncAttributeMaxDynamicSharedMemorySize, GEMM_SMEM);

    // 1) zero A bitmatrix + hop-1 accumulator + angles
    zero_kernel<<<1024, 256>>>();

    // 2) pre-split coeffs and weights to fp16 hi/lo
    split_kernel<<<(NN * DD / 4 + 255) / 256, 256>>>(coeffs, p_xh, p_xl, NN * DD);
    splitw_kernel<<<(3 * DD * DD / 4 + 255) / 256, 256>>>(W0, W1, W2, p_wh, p_wl);

    // 3) MLP: layers 1-2 split-fp16 GEMM+PReLU; layer 3 fused with output head
    dim3 ggrid(DD / BN, NN / BM);   // (4, 32) = 128 CTAs
    tc_gemm<1><<<ggrid, 256, GEMM_SMEM>>>(p_xh, p_xl, p_wh + 0 * DD * DD, p_wl + 0 * DD * DD,
                                          b0,      a0,  nullptr, p_yh, p_yl);
    tc_gemm<1><<<ggrid, 256, GEMM_SMEM>>>(p_yh, p_yl, p_wh + 1 * DD * DD, p_wl + 1 * DD * DD,
                                          nullptr, a1p, nullptr, p_xh, p_xl);
    tc_gemm<2><<<ggrid, 256, GEMM_SMEM>>>(p_xh, p_xl, p_wh + 2 * DD * DD, p_wl + 2 * DD * DD,
                                          nullptr, a2p, Wo, nullptr, nullptr);

    // 4) edges: bit adjacency + hop-1 raw segment sum (bo folded in)
    edge_kernel<<<(E + 255) / 256, 256>>>(eidx, E, bo);
    a1_kernel<<<(NN + 255) / 256, 256>>>(bo);

    // 5) hop 2 (materializes A2 bits) and hop 3 (fused, writes output)
    hop2_kernel<<<NN, 128>>>();
    hop3_kernel<<<NN, 128>>>(out);
}

// round 12
// speedup vs baseline: 2.6993x; 1.0019x over previous
#include <cuda_runtime.h>
#include <cuda_bf16.h>
#include <cuda_fp16.h>
#include <cstdint>

// Problem constants (fixed by the dataset)
#define NN 4096      // nodes
#define DD 512       // feature dim
#define NW 128       // bitmask words per row (4096/32)

// ---------------- device scratch (no allocation allowed) ----------------
__device__ float    g_angles[NN];
__device__ float    g_acc[NN];
__device__ float    g_a1[NN];
__device__ float    g_a2[NN];
__device__ unsigned g_A [NN * NW];
__device__ unsigned g_A2[NN * NW];
// fp16 split buffers
__device__ __align__(16) __half g_xh[NN * DD];
__device__ __align__(16) __half g_xl[NN * DD];
__device__ __align__(16) __half g_yh[NN * DD];
__device__ __align__(16) __half g_yl[NN * DD];
__device__ __align__(16) __half g_wh[3 * DD * DD];
__device__ __align__(16) __half g_wl[3 * DD * DD];

// ---------------- zero scratch (deterministic per call) ----------------
__global__ void zero_kernel() {
    int idx = blockIdx.x * blockDim.x + threadIdx.x;
    int total = NN * NW;
    for (int i = idx; i < total; i += gridDim.x * blockDim.x) g_A[i] = 0u;
    if (idx < NN) { g_acc[idx] = 0.0f; g_angles[idx] = 0.0f; }
}

// ---------------- fp32 -> (fp16 hi, fp16 lo) split ----------------------
__device__ __forceinline__ void split_store(const float* __restrict__ src,
                                            __half* __restrict__ h,
                                            __half* __restrict__ l, int i)
{
    float4 v = *(const float4*)(src + i);
    __half hx = __float2half_rn(v.x), hy = __float2half_rn(v.y);
    __half hz = __float2half_rn(v.z), hw = __float2half_rn(v.w);
    __half2 h01 = __halves2half2(hx, hy), h23 = __halves2half2(hz, hw);
    __half2 l01 = __halves2half2(__float2half_rn(v.x - __half2float(hx)),
                                 __float2half_rn(v.y - __half2float(hy)));
    __half2 l23 = __halves2half2(__float2half_rn(v.z - __half2float(hz)),
                                 __float2half_rn(v.w - __half2float(hw)));
    *(__half2*)(h + i)     = h01;
    *(__half2*)(h + i + 2) = h23;
    *(__half2*)(l + i)     = l01;
    *(__half2*)(l + i + 2) = l23;
}

__global__ void split_kernel(const float* __restrict__ src,
                             __half* __restrict__ h, __half* __restrict__ l,
                             int n)
{
    int idx = blockIdx.x * blockDim.x + threadIdx.x;
    int i = idx * 4;
    if (i >= n) return;
    split_store(src, h, l, i);
}

// merged 3-weight split (W0, W1, W2 -> g_wh/g_wl slabs)
__global__ void splitw_kernel(const float* __restrict__ W0,
                              const float* __restrict__ W1,
                              const float* __restrict__ W2,
                              __half* __restrict__ h, __half* __restrict__ l)
{
    const int per = DD * DD / 4;
    int idx = blockIdx.x * blockDim.x + threadIdx.x;
    if (idx >= 3 * per) return;
    int arr = idx / per;
    int i = (idx - arr * per) * 4;
    const float* src = arr == 0 ? W0 : (arr == 1 ? W1 : W2);
    split_store(src, h + arr * DD * DD, l + arr * DD * DD, i);
}

// ======================================================================
//  3xFP16 split GEMM, cp.async 3-stage pipeline + ldmatrix + mma.sync:
//     Y = prelu(Xh@Wh^T + Xh@Wl^T + Xl@Wh^T + bias, alpha)
//  MODE 1: store Y as split fp16 pair. MODE 2: fused output head --
//          atomicAdd per-row partials of Y @ Wo^T into g_angles.
//  CTA: 128(M) x 128(N), 512 threads (16 warps 4x4), warp 32x32.
// ======================================================================
#define BM 128
#define BN 128
#define BK 32
#define NT 512
#define LDSH 40                     // padded row stride in halves
#define ARR_B  (128 * LDSH * 2)     // 10240 B per array
#define STAGE_B (4 * ARR_B)         // 40960 B per stage
#define NSTAGE 3
#define GEMM_SMEM (NSTAGE * STAGE_B)
#define NCH (DD / BK)               // 16

__device__ __forceinline__ void mma_f16_16n8k16(
    float c[4], const uint32_t a[4], const uint32_t b[2])
{
    asm volatile(
        "mma.sync.aligned.m16n8k16.row.col.f32.f16.f16.f32 "
        "{%0,%1,%2,%3}, {%4,%5,%6,%7}, {%8,%9}, {%0,%1,%2,%3};"
        : "+f"(c[0]), "+f"(c[1]), "+f"(c[2]), "+f"(c[3])
        : "r"(a[0]), "r"(a[1]), "r"(a[2]), "r"(a[3]),
          "r"(b[0]), "r"(b[1]));
}

__device__ __forceinline__ void ldsm_x4(uint32_t r[4], uint32_t addr) {
    asm volatile(
        "ldmatrix.sync.aligned.m8n8.x4.shared.b16 {%0,%1,%2,%3}, [%4];"
        : "=r"(r[0]), "=r"(r[1]), "=r"(r[2]), "=r"(r[3]) : "r"(addr));
}

__device__ __forceinline__ void cpa16(uint32_t dst, const void* src) {
    asm volatile("cp.async.cg.shared.global [%0], [%1], 16;"
                 :: "r"(dst), "l"(src) : "memory");
}

template <int MODE>
__global__ __launch_bounds__(NT, 1) void tc_gemm(
    const __half* __restrict__ Xh, const __half* __restrict__ Xl,
    const __half* __restrict__ Wh, const __half* __restrict__ Wl,
    const float* __restrict__ bias, const float* __restrict__ alpha,
    const float* __restrict__ Wo,
    __half* __restrict__ Yh, __half* __restrict__ Yl)
{
    extern __shared__ char sm[];

    const int tid  = threadIdx.x;
    const int lane = tid & 31;
    const int wid  = tid >> 5;          // 0..15
    const int g    = lane >> 2;
    const int t4   = lane & 3;
    const int mwarp = (wid >> 2) * 32;  // 0,32,64,96
    const int nwarp = (wid & 3) * 32;   // 0,32,64,96
    const int bm = blockIdx.y * BM;
    const int bn = blockIdx.x * BN;

    // cp.async mapping: per array, 512 x 16B ops; exactly 1 per thread
    const int crow = tid >> 2;      // 0..127
    const int cq   = tid & 3;       // 16B unit within 64B row chunk

    const int rowA = lane & 15;
    const int kofA = (lane & 16) ? 8 : 0;
    const int rowB = (lane & 7) + ((lane & 16) ? 8 : 0);
    const int kofB = (lane & 8) ? 8 : 0;

    const uint32_t smbase = (uint32_t)__cvta_generic_to_shared(sm);

    float acc[2][4][4];
#pragma unroll
    for (int i = 0; i < 2; ++i)
#pragma unroll
        for (int j = 0; j < 4; ++j)
#pragma unroll
            for (int q = 0; q < 4; ++q) acc[i][j][q] = 0.0f;

    auto issue = [&](int kc) {
        const uint32_t st = smbase + (uint32_t)(kc % NSTAGE) * STAGE_B;
        uint32_t so = (uint32_t)(crow * (LDSH * 2) + cq * 16);
        size_t goA = (size_t)(bm + crow) * DD + kc * BK + cq * 8;
        size_t goB = (size_t)(bn + crow) * DD + kc * BK + cq * 8;
        cpa16(st + 0 * ARR_B + so, Xh + goA);
        cpa16(st + 1 * ARR_B + so, Xl + goA);
        cpa16(st + 2 * ARR_B + so, Wh + goB);
        cpa16(st + 3 * ARR_B + so, Wl + goB);
        asm volatile("cp.async.commit_group;" ::: "memory");
    };

    issue(0);
    issue(1);

    for (int kc = 0; kc < NCH; ++kc) {
        if (kc < NCH - 1)
            asm volatile("cp.async.wait_group 1;" ::: "memory");
        else
            asm volatile("cp.async.wait_group 0;" ::: "memory");
        __syncthreads();
        if (kc + 2 < NCH) issue(kc + 2);

        const uint32_t st  = smbase + (uint32_t)(kc % NSTAGE) * STAGE_B;
        const uint32_t AhU = st;
        const uint32_t AlU = st + ARR_B;
        const uint32_t BhU = st + 2 * ARR_B;
        const uint32_t BlU = st + 3 * ARR_B;

#pragma unroll
        for (int ks = 0; ks < 2; ++ks) {
            uint32_t ah[2][4], al[2][4], bh[4][2], bl[4][2];
            const uint32_t aoff = (uint32_t)(rowA * LDSH + ks * 16 + kofA) * 2u;
            const uint32_t boff = (uint32_t)(rowB * LDSH + ks * 16 + kofB) * 2u;
#pragma unroll
            for (int mt = 0; mt < 2; ++mt) {
                uint32_t mb = (uint32_t)((mwarp + mt * 16) * LDSH) * 2u;
                ldsm_x4(ah[mt], AhU + mb + aoff);
                ldsm_x4(al[mt], AlU + mb + aoff);
            }
#pragma unroll
            for (int p = 0; p < 2; ++p) {
                uint32_t nb = (uint32_t)((nwarp + p * 16) * LDSH) * 2u;
                uint32_t rh[4], rl[4];
                ldsm_x4(rh, BhU + nb + boff);
                ldsm_x4(rl, BlU + nb + boff);
                bh[2 * p][0] = rh[0]; bh[2 * p][1] = rh[1];
                bh[2 * p + 1][0] = rh[2]; bh[2 * p + 1][1] = rh[3];
                bl[2 * p][0] = rl[0]; bl[2 * p][1] = rl[1];
                bl[2 * p + 1][0] = rl[2]; bl[2 * p + 1][1] = rl[3];
            }
#pragma unroll
            for (int mt = 0; mt < 2; ++mt)
#pragma unroll
                for (int nt = 0; nt < 4; ++nt) {
                    mma_f16_16n8k16(acc[mt][nt], ah[mt], bh[nt]);
                    mma_f16_16n8k16(acc[mt][nt], ah[mt], bl[nt]);
                    mma_f16_16n8k16(acc[mt][nt], al[mt], bh[nt]);
                }
        }
    }

    // ---- epilogue ----
    const float alv = alpha[0];
#pragma unroll
    for (int mt = 0; mt < 2; ++mt) {
        int r0 = bm + mwarp + mt * 16 + g;
        float p0 = 0.f, p1 = 0.f;
#pragma unroll
        for (int nt = 0; nt < 4; ++nt) {
            int cb = bn + nwarp + nt * 8 + 2 * t4;
            float b0 = 0.f, b1 = 0.f;
            if (bias) { b0 = bias[cb]; b1 = bias[cb + 1]; }
            float v0 = acc[mt][nt][0] + b0;
            float v1 = acc[mt][nt][1] + b1;
            float v2 = acc[mt][nt][2] + b0;
            float v3 = acc[mt][nt][3] + b1;
            v0 = v0 >= 0.f ? v0 : alv * v0;
            v1 = v1 >= 0.f ? v1 : alv * v1;
            v2 = v2 >= 0.f ? v2 : alv * v2;
            v3 = v3 >= 0.f ? v3 : alv * v3;
            if (MODE == 1) {
                __half h0 = __float2half_rn(v0), h1 = __float2half_rn(v1);
                __half h2 = __float2half_rn(v2), h3 = __float2half_rn(v3);
                __half2 lo01 = __halves2half2(__float2half_rn(v0 - __half2float(h0)),
                                              __float2half_rn(v1 - __half2float(h1)));
                __half2 lo23 = __halves2half2(__float2half_rn(v2 - __half2float(h2)),
                                              __float2half_rn(v3 - __half2float(h3)));
                *(__half2*)&Yh[(size_t)r0 * DD + cb]       = __halves2half2(h0, h1);
                *(__half2*)&Yl[(size_t)r0 * DD + cb]       = lo01;
                *(__half2*)&Yh[(size_t)(r0 + 8) * DD + cb] = __halves2half2(h2, h3);
                *(__half2*)&Yl[(size_t)(r0 + 8) * DD + cb] = lo23;
            } else {
                // fused output head: partial dot with Wo over this tile's cols
                float w0 = Wo[cb], w1 = Wo[cb + 1];
                p0 = fmaf(v0, w0, fmaf(v1, w1, p0));
                p1 = fmaf(v2, w0, fmaf(v3, w1, p1));
            }
        }
        if (MODE == 2) {
            p0 += __shfl_xor_sync(0xffffffffu, p0, 1);
            p0 += __shfl_xor_sync(0xffffffffu, p0, 2);
            p1 += __shfl_xor_sync(0xffffffffu, p1, 1);
            p1 += __shfl_xor_sync(0xffffffffu, p1, 2);
            if (t4 == 0) {
                atomicAdd(&g_angles[r0],     p0);
                atomicAdd(&g_angles[r0 + 8], p1);
            }
        }
    }
}

// ---------------- edge pass: build bit-adjacency + hop-1 segment sum ----
// angles_full(d) = g_angles[d] + bo  (bo folded in here)
__global__ void edge_kernel(const int* __restrict__ ei, int E,
                            const float* __restrict__ bo)
{
    int t = blockIdx.x * blockDim.x + threadIdx.x;
    if (t >= E) return;
    int s = ei[t];
    int d = ei[E + t];
    atomicOr(&g_A[s * NW + (d >> 5)], 1u << (d & 31));
    atomicAdd(&g_acc[s], g_angles[d] + bo[0]);   // duplicates count
}

__global__ void a1_kernel(const float* __restrict__ bo)
{
    int i = blockIdx.x * blockDim.x + threadIdx.x;
    if (i < NN) g_a1[i] = (g_angles[i] + bo[0]) + 0.25f * g_acc[i];  // (0.5)^2
}

// ======================================================================
//  Hop kernels: prefix-sum neighbor extraction + 8-way unrolled row-OR
//  + coalesced broadcast-masked gather.
// ======================================================================
#define NBR_CAP 4096

template <bool STORE_A2>
__device__ __forceinline__ void hop_body(
    const unsigned* __restrict__ nbrmat,
    const float*    __restrict__ vec,
    float scale, float* __restrict__ dst)
{
    const int i = blockIdx.x;
    const int t = threadIdx.x;  // 0..127

    __shared__ unsigned short s_nbr[NBR_CAP];
    __shared__ int   s_wtot[4];
    __shared__ int   s_deg;
    __shared__ unsigned swords[NW];
    __shared__ float red[NW];

    // --- extract this row's neighbor list (deterministic order) ---
    unsigned mybits = g_A[i * NW + t];
    int cnt = __popc(mybits);
    int incl = cnt;
#pragma unroll
    for (int o = 1; o < 32; o <<= 1) {
        int v = __shfl_up_sync(0xffffffffu, incl, o);
        if ((t & 31) >= o) incl += v;
    }
    if ((t & 31) == 31) s_wtot[t >> 5] = incl;
    __syncthreads();
    int base = incl - cnt;
#pragma unroll
    for (int w = 0; w < 4; ++w)
        if (w < (t >> 5)) base += s_wtot[w];
    int pos = base;
    unsigned bb = mybits;
    while (bb) {
        int b = __ffs(bb) - 1;
        bb &= bb - 1;
        s_nbr[pos++] = (unsigned short)(t * 32 + b);
    }
    if (t == 127) s_deg = base + cnt;
    __syncthreads();
    const int deg = s_deg;

    // --- OR neighbor rows (word t), 8-way ILP ---
    unsigned accw = 0u;
    int j = 0;
    for (; j + 8 <= deg; j += 8) {
        unsigned v0 = nbrmat[s_nbr[j]     * NW + t];
        unsigned v1 = nbrmat[s_nbr[j + 1] * NW + t];
        unsigned v2 = nbrmat[s_nbr[j + 2] * NW + t];
        unsigned v3 = nbrmat[s_nbr[j + 3] * NW + t];
        unsigned v4 = nbrmat[s_nbr[j + 4] * NW + t];
        unsigned v5 = nbrmat[s_nbr[j + 5] * NW + t];
        unsigned v6 = nbrmat[s_nbr[j + 6] * NW + t];
        unsigned v7 = nbrmat[s_nbr[j + 7] * NW + t];
        accw |= ((v0 | v1) | (v2 | v3)) | ((v4 | v5) | (v6 | v7));
    }
    for (; j < deg; ++j) accw |= nbrmat[s_nbr[j] * NW + t];

    if (STORE_A2) g_A2[i * NW + t] = accw;
    swords[t] = accw;
    __syncthreads();

    // --- coalesced masked gather: element k*128+t, warp-uniform word ---
    float p = 0.f;
#pragma unroll 4
    for (int k = 0; k < 32; ++k) {
        int idx = k * 128 + t;
        unsigned wrd = swords[idx >> 5];
        p += vec[idx] * (float)((wrd >> (idx & 31)) & 1u);
    }
    red[t] = p;
    __syncthreads();
#pragma unroll
    for (int s = 64; s; s >>= 1) {
        if (t < s) red[t] += red[t + s];
        __syncthreads();
    }
    if (t == 0) dst[i] = vec[i] + scale * red[0];
}

__global__ __launch_bounds__(128) void hop2_kernel()
{
    hop_body<true>(g_A, g_a1, 1.0f / 9.0f, g_a2);
}

__global__ __launch_bounds__(128) void hop3_kernel(float* __restrict__ out)
{
    hop_body<false>(g_A2, g_a2, 1.0f / 16.0f, out);
}

// ---------------------------- launch ------------------------------------
extern "C" void kernel_launch(void* const* d_in, const int* in_sizes, int n_in,
                              void* d_out, int out_size)
{
    const float* coeffs = (const float*)d_in[0];
    const int*   eidx   = (const int*)  d_in[1];
    const float* W0     = (const float*)d_in[2];
    const float* b0     = (const float*)d_in[3];
    const float* a0     = (const float*)d_in[4];
    const float* W1     = (const float*)d_in[5];
    const float* a1p    = (const float*)d_in[6];
    const float* W2     = (const float*)d_in[7];
    const float* a2p    = (const float*)d_in[8];
    const float* Wo     = (const float*)d_in[9];
    const float* bo     = (const float*)d_in[10];
    float* out = (float*)d_out;

    const int E = in_sizes[1] / 2;

    __half *p_xh, *p_xl, *p_yh, *p_yl, *p_wh, *p_wl;
    cudaGetSymbolAddress((void**)&p_xh, g_xh);
    cudaGetSymbolAddress((void**)&p_xl, g_xl);
    cudaGetSymbolAddress((void**)&p_yh, g_yh);
    cudaGetSymbolAddress((void**)&p_yl, g_yl);
    cudaGetSymbolAddress((void**)&p_wh, g_wh);
    cudaGetSymbolAddress((void**)&p_wl, g_wl);

    cudaFuncSetAttribute(tc_gemm<1>, cudaFuncAttributeMaxDynamicSharedMemorySize, GEMM_SMEM);
    cudaFuncSetAttribute(tc_gemm<2>, cudaFuncAttributeMaxDynamicSharedMemorySize, GEMM_SMEM);

    // 1) zero A bitmatrix + hop-1 accumulator + angles
    zero_kernel<<<1024, 256>>>();

    // 2) pre-split coeffs and weights to fp16 hi/lo
    split_kernel<<<(NN * DD / 4 + 255) / 256, 256>>>(coeffs, p_xh, p_xl, NN * DD);
    splitw_kernel<<<(3 * DD * DD / 4 + 255) / 256, 256>>>(W0, W1, W2, p_wh, p_wl);

    // 3) MLP: layers 1-2 split-fp16 GEMM+PReLU; layer 3 fused with output head
    dim3 ggrid(DD / BN, NN / BM);   // (4, 32) = 128 CTAs
    tc_gemm<1><<<ggrid, NT, GEMM_SMEM>>>(p_xh, p_xl, p_wh + 0 * DD * DD, p_wl + 0 * DD * DD,
                                         b0,      a0,  nullptr, p_yh, p_yl);
    tc_gemm<1><<<ggrid, NT, GEMM_SMEM>>>(p_yh, p_yl, p_wh + 1 * DD * DD, p_wl + 1 * DD * DD,
                                         nullptr, a1p, nullptr, p_xh, p_xl);
    tc_gemm<2><<<ggrid, NT, GEMM_SMEM>>>(p_xh, p_xl, p_wh + 2 * DD * DD, p_wl + 2 * DD * DD,
                                         nullptr, a2p, Wo, nullptr, nullptr);

    // 4) edges: bit adjacency + hop-1 raw segment sum (bo folded in)
    edge_kernel<<<(E + 255) / 256, 256>>>(eidx, E, bo);
    a1_kernel<<<(NN + 255) / 256, 256>>>(bo);

    // 5) hop 2 (materializes A2 bits) and hop 3 (fused, writes output)
    hop2_kernel<<<NN, 128>>>();
    hop3_kernel<<<NN, 128>>>(out);
}